// round 3
// baseline (speedup 1.0000x reference)
#include <cuda_runtime.h>
#include <math.h>

#define Hh 100
#define Nn 1024
#define Bb 64
#define Ll 16
#define Ej 2048
#define Jn 40000

// ---------------- device scratch (no allocs allowed) ----------------
__device__ float g_h  [Nn*Hh];     // embedded h
__device__ float g_m  [Nn*Hh];     // h @ ggc_w
__device__ float g_agg[Nn*Hh];     // scatter target
__device__ float g_h2 [Nn*Hh];     // after GRU  (== v)
__device__ float g_vtT[Bb*Hh*Ll];  // vt transposed: [b][h][l]
__device__ float g_vT [Bb*Hh*Ll];  // v  transposed: [b][h][l]
__device__ float g_sh [Bb*Hh];     // s_h
__device__ float g_eT [Hh*Jn];     // embed transposed [h][j]  (16 MB, L2-resident)

// ---------------- f32x2 packed helpers ----------------
__device__ __forceinline__ unsigned long long pack2(float x, float y) {
    unsigned long long r;
    asm("mov.b64 %0, {%1, %2};" : "=l"(r) : "f"(x), "f"(y));
    return r;
}
__device__ __forceinline__ void fma2(unsigned long long& d, unsigned long long a, unsigned long long b) {
    asm("fma.rn.f32x2 %0, %1, %2, %0;" : "+l"(d) : "l"(a), "l"(b));
}
__device__ __forceinline__ void unpack2(unsigned long long v, float& x, float& y) {
    asm("mov.b64 {%0, %1}, %2;" : "=f"(x), "=f"(y) : "l"(v));
}
__device__ __forceinline__ float sigm(float x) { return 1.0f / (1.0f + __expf(-x)); }

// ---------------- K0: transpose embed -> g_eT ----------------
__global__ void k_transpose(const float* __restrict__ embed) {
    __shared__ float tile[32][33];
    int hb = blockIdx.x * 32;          // h tile (0,32,64,96)
    int jb = blockIdx.y * 32;          // j tile
    int tx = threadIdx.x, ty = threadIdx.y;   // 32 x 8
    #pragma unroll
    for (int r = ty; r < 32; r += 8) {
        int j = jb + r, h = hb + tx;
        tile[r][tx] = (h < Hh) ? embed[(size_t)j * Hh + h] : 0.0f;
    }
    __syncthreads();
    #pragma unroll
    for (int r = ty; r < 32; r += 8) {
        int h = hb + r, j = jb + tx;
        if (h < Hh) g_eT[(size_t)h * Jn + j] = tile[tx][r];
    }
}

// ---------------- K1: gather h, zero agg, m = h @ ggc_w ----------------
__global__ void k_gather(const int* __restrict__ x, const float* __restrict__ embed,
                         const float* __restrict__ ggc) {
    __shared__ float hs[Hh];
    int i = blockIdx.x, t = threadIdx.x;
    if (t < Hh) {
        float v = embed[(size_t)x[i] * Hh + t];
        hs[t] = v;
        g_h[i * Hh + t] = v;
        g_agg[i * Hh + t] = 0.0f;
    }
    __syncthreads();
    if (t < Hh) {
        float acc = 0.0f;
        #pragma unroll 4
        for (int c = 0; c < Hh; c++) acc = fmaf(hs[c], ggc[c * Hh + t], acc);
        g_m[i * Hh + t] = acc;
    }
}

// ---------------- K2: scatter-add over edges ----------------
__global__ void k_scatter(const int* __restrict__ ei, const float* __restrict__ ew) {
    int e = blockIdx.x, t = threadIdx.x;
    if (t < Hh) {
        int s = ei[e], d = ei[Ej + e];
        atomicAdd(&g_agg[d * Hh + t], ew[e] * g_m[s * Hh + t]);
    }
}

// ---------------- K3: GRU cell ----------------
__global__ void k_gru(const float* __restrict__ wih, const float* __restrict__ whh,
                      const float* __restrict__ bih, const float* __restrict__ bhh) {
    __shared__ float as_[Hh], hs[Hh];
    int i = blockIdx.x, t = threadIdx.x;
    if (t < Hh) { as_[t] = g_agg[i * Hh + t]; hs[t] = g_h[i * Hh + t]; }
    __syncthreads();
    if (t < Hh) {
        float gr = bih[t], gz = bih[Hh + t], gn = bih[2 * Hh + t];
        float hr = bhh[t], hz = bhh[Hh + t], hn = bhh[2 * Hh + t];
        const float* wr = wih + t * Hh;
        const float* wz = wih + (Hh + t) * Hh;
        const float* wn = wih + (2 * Hh + t) * Hh;
        const float* ur = whh + t * Hh;
        const float* uz = whh + (Hh + t) * Hh;
        const float* un = whh + (2 * Hh + t) * Hh;
        #pragma unroll 4
        for (int c = 0; c < Hh; c++) {
            float a = as_[c], h = hs[c];
            gr = fmaf(a, wr[c], gr); gz = fmaf(a, wz[c], gz); gn = fmaf(a, wn[c], gn);
            hr = fmaf(h, ur[c], hr); hz = fmaf(h, uz[c], hz); hn = fmaf(h, un[c], hn);
        }
        float r  = sigm(gr + hr);
        float zg = sigm(gz + hz);
        float ng = tanhf(gn + r * hn);
        g_h2[i * Hh + t] = (1.0f - zg) * ng + zg * hs[t];
    }
}

// ---------------- K4: attention readout, s_h, vt (per batch b) ----------------
__global__ void k_attn(const float* __restrict__ W1w, const float* __restrict__ W1b,
                       const float* __restrict__ W2w, const float* __restrict__ W2b,
                       const float* __restrict__ Wtw, const float* __restrict__ Wtb,
                       const float* __restrict__ qw,  const float* __restrict__ qb,
                       const float* __restrict__ W3w, const float* __restrict__ W3b) {
    __shared__ float vs[Ll * Hh];      // v[l][c]
    __shared__ float t1[Hh];
    __shared__ float a_s[Ll * Hh];
    __shared__ float alpha_s[Ll];
    __shared__ float sg[Hh];
    int b = blockIdx.x, t = threadIdx.x;

    for (int i = t; i < Ll * Hh; i += 128) vs[i] = g_h2[b * Ll * Hh + i];
    __syncthreads();

    // t1 = s_l @ W1^T + b1   (s_l = v[15])
    if (t < Hh) {
        float acc = W1b[t];
        const float* w = W1w + t * Hh;
        #pragma unroll 4
        for (int c = 0; c < Hh; c++) acc = fmaf(vs[15 * Hh + c], w[c], acc);
        t1[t] = acc;
    }
    __syncthreads();

    // a = sigmoid(t1 + v @ W2^T + b2)
    for (int idx = t; idx < Ll * Hh; idx += 128) {
        int l = idx / Hh, k = idx % Hh;
        float acc = W2b[k];
        const float* w = W2w + k * Hh;
        const float* vrow = vs + l * Hh;
        #pragma unroll 4
        for (int c = 0; c < Hh; c++) acc = fmaf(vrow[c], w[c], acc);
        a_s[idx] = sigm(t1[k] + acc);
    }
    __syncthreads();

    // alpha[l] = a[l] . q_w + q_b
    if (t < Ll) {
        float acc = qb[0];
        #pragma unroll 4
        for (int k = 0; k < Hh; k++) acc = fmaf(a_s[t * Hh + k], qw[k], acc);
        alpha_s[t] = acc;
    }
    __syncthreads();

    // s_g[c] = sum_l alpha[l] * v[l][c]
    if (t < Hh) {
        float acc = 0.0f;
        #pragma unroll
        for (int l = 0; l < Ll; l++) acc = fmaf(alpha_s[l], vs[l * Hh + t], acc);
        sg[t] = acc;
    }
    __syncthreads();

    // s_h[k] = [s_l ; s_g] @ W3^T + b3
    if (t < Hh) {
        float acc = W3b[t];
        const float* w = W3w + t * 2 * Hh;
        #pragma unroll 4
        for (int c = 0; c < Hh; c++)
            acc = fmaf(vs[15 * Hh + c], w[c], fmaf(sg[c], w[Hh + c], acc));
        g_sh[b * Hh + t] = acc;
    }

    // vt = v @ Wt^T + bt  -> store transposed [h][l]; also v transposed
    for (int idx = t; idx < Ll * Hh; idx += 128) {
        int l = idx / Hh, k = idx % Hh;
        float acc = Wtb[k];
        const float* w = Wtw + k * Hh;
        const float* vrow = vs + l * Hh;
        #pragma unroll 4
        for (int c = 0; c < Hh; c++) acc = fmaf(vrow[c], w[c], acc);
        g_vtT[b * Hh * Ll + k * Ll + l] = acc;
        g_vT [b * Hh * Ll + k * Ll + l] = vs[l * Hh + k];
    }
}

// ---------------- K5: the big fused kernel ----------------
// z[b,j] = s_h[b].e_j + sum_l softmax_l(vt[b,l].e_j) * (v[b,l].e_j)
// Thread owns 2 adjacent j's; packed f32x2 FMAs; e from transposed embed (coalesced).
__global__ __launch_bounds__(256, 2) void k_z(float* __restrict__ z) {
    __shared__ __align__(16) float s_vt[Hh * Ll];
    __shared__ __align__(16) float s_v [Hh * Ll];
    __shared__ float s_sh[Hh];

    int b = blockIdx.y, t = threadIdx.x;
    for (int i = t; i < Hh * Ll; i += 256) {
        s_vt[i] = g_vtT[b * Hh * Ll + i];
        s_v [i] = g_vT [b * Hh * Ll + i];
    }
    if (t < Hh) s_sh[t] = g_sh[b * Hh + t];
    __syncthreads();

    int j0 = blockIdx.x * 512 + t * 2;          // even; j0 and j0+1 owned
    bool ok = (j0 < Jn);
    int jj = ok ? j0 : 0;
    const float* ebase = g_eT + jj;

    unsigned long long p0[8], p1[8], c0[8], c1[8];
    #pragma unroll
    for (int q = 0; q < 8; q++) { p0[q] = p1[q] = c0[q] = c1[q] = 0ull; }
    float sa0 = 0.0f, sa1 = 0.0f;

    float2 ecur[4];
    #pragma unroll
    for (int u = 0; u < 4; u++) ecur[u] = *(const float2*)(ebase + (size_t)u * Jn);

    for (int hc = 0; hc < 25; hc++) {
        float2 enx[4];
        #pragma unroll
        for (int u = 0; u < 4; u++) {
            int hn = (hc < 24) ? (hc * 4 + 4 + u) : 0;
            enx[u] = *(const float2*)(ebase + (size_t)hn * Jn);
        }
        #pragma unroll
        for (int u = 0; u < 4; u++) {
            int h = hc * 4 + u;
            float e0 = ecur[u].x, e1 = ecur[u].y;
            unsigned long long ee0 = pack2(e0, e0);
            unsigned long long ee1 = pack2(e1, e1);
            const ulonglong2* vtr = (const ulonglong2*)(s_vt + h * Ll);
            const ulonglong2* vvr = (const ulonglong2*)(s_v  + h * Ll);
            #pragma unroll
            for (int q = 0; q < 4; q++) {
                ulonglong2 wa = vtr[q];
                fma2(p0[2 * q],     wa.x, ee0);
                fma2(p0[2 * q + 1], wa.y, ee0);
                fma2(p1[2 * q],     wa.x, ee1);
                fma2(p1[2 * q + 1], wa.y, ee1);
                ulonglong2 wb = vvr[q];
                fma2(c0[2 * q],     wb.x, ee0);
                fma2(c0[2 * q + 1], wb.y, ee0);
                fma2(c1[2 * q],     wb.x, ee1);
                fma2(c1[2 * q + 1], wb.y, ee1);
            }
            sa0 = fmaf(s_sh[h], e0, sa0);
            sa1 = fmaf(s_sh[h], e1, sa1);
        }
        #pragma unroll
        for (int u = 0; u < 4; u++) ecur[u] = enx[u];
    }

    if (ok) {
        float pv[16], cv[16];
        #pragma unroll
        for (int q = 0; q < 8; q++) { unpack2(p0[q], pv[2 * q], pv[2 * q + 1]); unpack2(c0[q], cv[2 * q], cv[2 * q + 1]); }
        float mx = pv[0];
        #pragma unroll
        for (int l = 1; l < 16; l++) mx = fmaxf(mx, pv[l]);
        float se = 0.0f, ac = 0.0f;
        #pragma unroll
        for (int l = 0; l < 16; l++) { float ex = __expf(pv[l] - mx); se += ex; ac = fmaf(ex, cv[l], ac); }
        float z0 = sa0 + ac / se;

        #pragma unroll
        for (int q = 0; q < 8; q++) { unpack2(p1[q], pv[2 * q], pv[2 * q + 1]); unpack2(c1[q], cv[2 * q], cv[2 * q + 1]); }
        mx = pv[0];
        #pragma unroll
        for (int l = 1; l < 16; l++) mx = fmaxf(mx, pv[l]);
        se = 0.0f; ac = 0.0f;
        #pragma unroll
        for (int l = 0; l < 16; l++) { float ex = __expf(pv[l] - mx); se += ex; ac = fmaf(ex, cv[l], ac); }
        float z1 = sa1 + ac / se;

        *(float2*)(z + (size_t)b * Jn + j0) = make_float2(z0, z1);
    }
}

// ---------------- launch ----------------
extern "C" void kernel_launch(void* const* d_in, const int* in_sizes, int n_in,
                              void* d_out, int out_size) {
    const int*   x     = (const int*)  d_in[0];
    const int*   ei    = (const int*)  d_in[1];
    const float* ew    = (const float*)d_in[2];
    // d_in[3] = batch (unused; layout implied by reshape)
    const float* embed = (const float*)d_in[4];
    const float* ggc   = (const float*)d_in[5];
    const float* wih   = (const float*)d_in[6];
    const float* whh   = (const float*)d_in[7];
    const float* bih   = (const float*)d_in[8];
    const float* bhh   = (const float*)d_in[9];
    const float* W1w   = (const float*)d_in[10];
    const float* W1b   = (const float*)d_in[11];
    const float* W2w   = (const float*)d_in[12];
    const float* W2b   = (const float*)d_in[13];
    const float* Wtw   = (const float*)d_in[14];
    const float* Wtb   = (const float*)d_in[15];
    const float* qw    = (const float*)d_in[16];
    const float* qb    = (const float*)d_in[17];
    const float* W3w   = (const float*)d_in[18];
    const float* W3b   = (const float*)d_in[19];
    float* z = (float*)d_out;

    k_transpose<<<dim3(4, 1250), dim3(32, 8)>>>(embed);
    k_gather<<<Nn, 128>>>(x, embed, ggc);
    k_scatter<<<Ej, 128>>>(ei, ew);
    k_gru<<<Nn, 128>>>(wih, whh, bih, bhh);
    k_attn<<<Bb, 128>>>(W1w, W1b, W2w, W2b, Wtw, Wtb, qw, qb, W3w, W3b);
    k_z<<<dim3(79, Bb), 256>>>(z);
}

// round 5
// speedup vs baseline: 1.3326x; 1.3326x over previous
#include <cuda_runtime.h>
#include <cuda_bf16.h>
#include <math.h>
#include <stdint.h>

#define Hh 100
#define Nn 1024
#define Bb 64
#define Ll 16
#define Ej 2048
#define Jn 40000
#define Jpad 40064
#define KE 336            // extended K: [112 | 112 | 112]
#define ROWB 672          // bytes per packed row in global (336 bf16)
#define SSTR 688          // smem row stride bytes (padded, conflict-free)
#define JT 64             // j rows per CTA
#define NJT (Jpad/JT)     // 626
#define BSPLIT 4
#define BPC (Bb/BSPLIT)   // 16 batches per CTA
#define SM_E (JT*SSTR)            // 44032
#define SM_CBUF (32*SSTR)         // 22016
#define SM_TOTAL (SM_E + 2*SM_CBUF)  // 88064

// ---------------- device scratch (no runtime allocs) ----------------
__device__ float g_h   [Nn*Hh];
__device__ float g_m   [Nn*Hh];
__device__ float g_agg [Nn*Hh];
__device__ float g_h2  [Nn*Hh];
__device__ float g_vtT [Bb*Hh*Ll];   // [b][h][l]
__device__ float g_vT  [Bb*Hh*Ll];   // [b][h][l]
__device__ float g_sh  [Bb*Hh];
__device__ float g_wihT[Hh*300];
__device__ float g_whhT[Hh*300];
// packed e: [j][KE] bf16, A-layout chunks [hi | lo | hi]
__device__ __align__(16) __nv_bfloat16 g_epk[(size_t)Jpad*KE];
// packed coef: [b][32][KE] bf16, B-layout chunks [hi | hi | lo]
__device__ __align__(16) __nv_bfloat16 g_cpk[(size_t)Bb*32*KE];

__device__ __forceinline__ float sigm(float x) { return 1.0f / (1.0f + __expf(-x)); }

__device__ __forceinline__ uint32_t smem_u32(const void* p) {
    uint32_t a;
    asm("{ .reg .u64 t; cvta.to.shared.u64 t, %1; cvt.u32.u64 %0, t; }" : "=r"(a) : "l"(p));
    return a;
}
__device__ __forceinline__ void cp16(uint32_t dst, const void* src) {
    asm volatile("cp.async.cg.shared.global [%0], [%1], 16;" :: "r"(dst), "l"(src) : "memory");
}

// ================= K_prep_e: embed -> packed bf16 rows =================
// out chunk layout (A): k<112 -> hi(h=k); 112..223 -> lo(h=k-112); 224..335 -> hi(h=k-224)
__global__ void k_prep_e(const float* __restrict__ embed) {
    int idx = blockIdx.x * 256 + threadIdx.x;   // over Jpad*168 pairs
    if (idx >= Jpad * (KE/2)) return;
    int j  = idx / (KE/2);
    int kp = (idx - j * (KE/2)) * 2;
    __nv_bfloat16 o[2];
    #pragma unroll
    for (int i = 0; i < 2; i++) {
        int k = kp + i;
        int chunk = k / 112;
        int h = k - chunk * 112;
        float v = (j < Jn && h < Hh) ? embed[(size_t)j * Hh + h] : 0.0f;
        __nv_bfloat16 hi = __float2bfloat16(v);
        __nv_bfloat16 lo = __float2bfloat16(v - __bfloat162float(hi));
        o[i] = (chunk == 1) ? lo : hi;
    }
    *(uint32_t*)(g_epk + (size_t)j * KE + kp) = *(uint32_t*)o;
}

// ================= K_prep_c: coef rows (vt, v+sh) packed =================
// out chunk layout (B): k<112 -> hi; 112..223 -> hi; 224..335 -> lo
__global__ void k_prep_c() {
    int idx = blockIdx.x * 256 + threadIdx.x;   // over Bb*32*KE
    if (idx >= Bb * 32 * KE) return;
    int k = idx % KE;
    int r = (idx / KE) & 31;
    int b = idx / (KE * 32);
    int chunk = k / 112;
    int h = k - chunk * 112;
    float v = 0.0f;
    if (h < Hh) {
        if (r < 16) v = g_vtT[b * Hh * Ll + h * Ll + r];
        else        v = g_vT [b * Hh * Ll + h * Ll + (r - 16)] + g_sh[b * Hh + h];
    }
    __nv_bfloat16 hi = __float2bfloat16(v);
    __nv_bfloat16 lo = __float2bfloat16(v - __bfloat162float(hi));
    g_cpk[idx] = (chunk == 2) ? lo : hi;
}

// ================= K_wt: transpose GRU weights =================
__global__ void k_wt(const float* __restrict__ wih, const float* __restrict__ whh) {
    int i = blockIdx.x * 256 + threadIdx.x;
    if (i < 300 * Hh) {
        int r = i / Hh, c = i % Hh;
        g_wihT[c * 300 + r] = wih[i];
        g_whhT[c * 300 + r] = whh[i];
    }
}

// ================= K1: gather + m = h @ ggc_w =================
__global__ void k_gather(const int* __restrict__ x, const float* __restrict__ embed,
                         const float* __restrict__ ggc) {
    __shared__ float hs[Hh];
    int i = blockIdx.x, t = threadIdx.x;
    if (t < Hh) {
        float v = embed[(size_t)x[i] * Hh + t];
        hs[t] = v;
        g_h[i * Hh + t] = v;
        g_agg[i * Hh + t] = 0.0f;
    }
    __syncthreads();
    if (t < Hh) {
        float acc = 0.0f;
        #pragma unroll 4
        for (int c = 0; c < Hh; c++) acc = fmaf(hs[c], ggc[c * Hh + t], acc);
        g_m[i * Hh + t] = acc;
    }
}

// ================= K2: scatter-add =================
__global__ void k_scatter(const int* __restrict__ ei, const float* __restrict__ ew) {
    int e = blockIdx.x, t = threadIdx.x;
    if (t < Hh) {
        int s = ei[e], d = ei[Ej + e];
        atomicAdd(&g_agg[d * Hh + t], ew[e] * g_m[s * Hh + t]);
    }
}

// ================= K3: GRU (coalesced transposed weights, 4 nodes/block) ===
__global__ void k_gru2(const float* __restrict__ bih, const float* __restrict__ bhh) {
    __shared__ float a_s[4][Hh], h_s[4][Hh];
    __shared__ float gi_s[4][300], gh_s[4][300];
    int nb = blockIdx.x * 4;
    int t = threadIdx.x;             // block 416
    for (int i = t; i < 4 * Hh; i += 416) {
        int n = i / Hh, c = i % Hh;
        a_s[n][c] = g_agg[(nb + n) * Hh + c];
        h_s[n][c] = g_h  [(nb + n) * Hh + c];
    }
    __syncthreads();
    if (t < 300) {
        float ai0 = bih[t], ai1 = ai0, ai2 = ai0, ai3 = ai0;
        float ah0 = bhh[t], ah1 = ah0, ah2 = ah0, ah3 = ah0;
        #pragma unroll 4
        for (int c = 0; c < Hh; c++) {
            float wv = g_wihT[c * 300 + t];
            float uv = g_whhT[c * 300 + t];
            ai0 = fmaf(a_s[0][c], wv, ai0); ah0 = fmaf(h_s[0][c], uv, ah0);
            ai1 = fmaf(a_s[1][c], wv, ai1); ah1 = fmaf(h_s[1][c], uv, ah1);
            ai2 = fmaf(a_s[2][c], wv, ai2); ah2 = fmaf(h_s[2][c], uv, ah2);
            ai3 = fmaf(a_s[3][c], wv, ai3); ah3 = fmaf(h_s[3][c], uv, ah3);
        }
        gi_s[0][t] = ai0; gi_s[1][t] = ai1; gi_s[2][t] = ai2; gi_s[3][t] = ai3;
        gh_s[0][t] = ah0; gh_s[1][t] = ah1; gh_s[2][t] = ah2; gh_s[3][t] = ah3;
    }
    __syncthreads();
    if (t < 400) {
        int n = t / Hh, k = t % Hh;
        float r  = sigm(gi_s[n][k]         + gh_s[n][k]);
        float zg = sigm(gi_s[n][Hh + k]    + gh_s[n][Hh + k]);
        float ng = tanhf(gi_s[n][2*Hh + k] + r * gh_s[n][2*Hh + k]);
        g_h2[(nb + n) * Hh + k] = (1.0f - zg) * ng + zg * h_s[n][k];
    }
}

// ================= K4: attention readout =================
__global__ void k_attn(const float* __restrict__ W1w, const float* __restrict__ W1b,
                       const float* __restrict__ W2w, const float* __restrict__ W2b,
                       const float* __restrict__ Wtw, const float* __restrict__ Wtb,
                       const float* __restrict__ qw,  const float* __restrict__ qb,
                       const float* __restrict__ W3w, const float* __restrict__ W3b) {
    __shared__ float vs[Ll * Hh];
    __shared__ float t1[Hh];
    __shared__ float a_s[Ll * Hh];
    __shared__ float alpha_s[Ll];
    __shared__ float sg[Hh];
    int b = blockIdx.x, t = threadIdx.x;

    for (int i = t; i < Ll * Hh; i += 128) vs[i] = g_h2[b * Ll * Hh + i];
    __syncthreads();

    if (t < Hh) {
        float acc = W1b[t];
        const float* w = W1w + t * Hh;
        #pragma unroll 4
        for (int c = 0; c < Hh; c++) acc = fmaf(vs[15 * Hh + c], w[c], acc);
        t1[t] = acc;
    }
    __syncthreads();

    for (int idx = t; idx < Ll * Hh; idx += 128) {
        int l = idx / Hh, k = idx % Hh;
        float acc = W2b[k];
        const float* w = W2w + k * Hh;
        const float* vrow = vs + l * Hh;
        #pragma unroll 4
        for (int c = 0; c < Hh; c++) acc = fmaf(vrow[c], w[c], acc);
        a_s[idx] = sigm(t1[k] + acc);
    }
    __syncthreads();

    if (t < Ll) {
        float acc = qb[0];
        #pragma unroll 4
        for (int k = 0; k < Hh; k++) acc = fmaf(a_s[t * Hh + k], qw[k], acc);
        alpha_s[t] = acc;
    }
    __syncthreads();

    if (t < Hh) {
        float acc = 0.0f;
        #pragma unroll
        for (int l = 0; l < Ll; l++) acc = fmaf(alpha_s[l], vs[l * Hh + t], acc);
        sg[t] = acc;
    }
    __syncthreads();

    if (t < Hh) {
        float acc = W3b[t];
        const float* w = W3w + t * 2 * Hh;
        #pragma unroll 4
        for (int c = 0; c < Hh; c++)
            acc = fmaf(vs[15 * Hh + c], w[c], fmaf(sg[c], w[Hh + c], acc));
        g_sh[b * Hh + t] = acc;
    }

    for (int idx = t; idx < Ll * Hh; idx += 128) {
        int l = idx / Hh, k = idx % Hh;
        float acc = Wtb[k];
        const float* w = Wtw + k * Hh;
        const float* vrow = vs + l * Hh;
        #pragma unroll 4
        for (int c = 0; c < Hh; c++) acc = fmaf(vrow[c], w[c], acc);
        g_vtT[b * Hh * Ll + k * Ll + l] = acc;
        g_vT [b * Hh * Ll + k * Ll + l] = vs[l * Hh + k];
    }
}

// ================= K5: HMMA fused GEMM + softmax epilogue =================
// D[j,r] = e_ext[j,:] . coef_ext[r,:]; r 0-15 = p (vt), 16-31 = c' (v + s_h)
// z[b,j] = sum_l softmax(p)_l * c'_l
__global__ void __launch_bounds__(128, 2) k_ztc(float* __restrict__ z) {
    extern __shared__ __align__(128) char sm[];
    const uint32_t smE = smem_u32(sm);
    const uint32_t smC = smE + SM_E;
    int tid = threadIdx.x, warp = tid >> 5, lane = tid & 31;
    int jt = blockIdx.x, b0 = blockIdx.y * BPC;

    // load e tile (64 rows x 672B) into padded smem
    {
        const char* src = (const char*)g_epk + (size_t)jt * JT * ROWB;
        for (int i = tid; i < JT * 42; i += 128) {
            int r = i / 42, c = i - r * 42;
            cp16(smE + (uint32_t)r * SSTR + c * 16, src + (size_t)r * ROWB + c * 16);
        }
    }
    // load coef for b0 into buf 0
    {
        const char* src = (const char*)g_cpk + (size_t)b0 * 32 * ROWB;
        for (int i = tid; i < 32 * 42; i += 128) {
            int r = i / 42, c = i - r * 42;
            cp16(smC + (uint32_t)r * SSTR + c * 16, src + (size_t)r * ROWB + c * 16);
        }
    }
    asm volatile("cp.async.commit_group;" ::: "memory");
    asm volatile("cp.async.wait_group 0;" ::: "memory");
    __syncthreads();

    // ldmatrix lane addressing (stride 688B is conflict-free)
    const uint32_t aBase = smE + (uint32_t)(warp * 16 + (lane & 15)) * SSTR + ((lane >> 4) << 4);
    const uint32_t bOff  = (uint32_t)(lane & 7) * SSTR + (((lane >> 3) & 1) << 4);

    for (int bi = 0; bi < BPC; bi++) {
        if (bi + 1 < BPC) {
            const char* src = (const char*)g_cpk + (size_t)(b0 + bi + 1) * 32 * ROWB;
            uint32_t dst = smC + (uint32_t)((bi + 1) & 1) * SM_CBUF;
            for (int i = tid; i < 32 * 42; i += 128) {
                int r = i / 42, c = i - r * 42;
                cp16(dst + (uint32_t)r * SSTR + c * 16, src + (size_t)r * ROWB + c * 16);
            }
            asm volatile("cp.async.commit_group;" ::: "memory");
        }
        const uint32_t bBase = smC + (uint32_t)(bi & 1) * SM_CBUF + bOff;

        float acc[4][4];
        #pragma unroll
        for (int n = 0; n < 4; n++)
            #pragma unroll
            for (int q = 0; q < 4; q++) acc[n][q] = 0.0f;

        #pragma unroll
        for (int ks = 0; ks < 21; ks++) {
            uint32_t a0, a1, a2, a3;
            asm volatile("ldmatrix.sync.aligned.m8n8.x4.shared.b16 {%0,%1,%2,%3}, [%4];"
                         : "=r"(a0), "=r"(a1), "=r"(a2), "=r"(a3)
                         : "r"(aBase + ks * 32));
            #pragma unroll
            for (int nt = 0; nt < 4; nt++) {
                uint32_t bb0, bb1;
                asm volatile("ldmatrix.sync.aligned.m8n8.x2.shared.b16 {%0,%1}, [%2];"
                             : "=r"(bb0), "=r"(bb1)
                             : "r"(bBase + nt * (8 * SSTR) + ks * 32));
                asm volatile(
                    "mma.sync.aligned.m16n8k16.row.col.f32.bf16.bf16.f32 "
                    "{%0,%1,%2,%3}, {%4,%5,%6,%7}, {%8,%9}, {%0,%1,%2,%3};"
                    : "+f"(acc[nt][0]), "+f"(acc[nt][1]), "+f"(acc[nt][2]), "+f"(acc[nt][3])
                    : "r"(a0), "r"(a1), "r"(a2), "r"(a3), "r"(bb0), "r"(bb1));
            }
        }

        // epilogue: fragment rows jA = g, jB = g+8; cols: nt*8 + 2*(lane&3)+{0,1}
        int b = b0 + bi;
        int jA = jt * JT + warp * 16 + (lane >> 2);
        {   // row A
            float p0 = acc[0][0], p1 = acc[0][1], p2 = acc[1][0], p3 = acc[1][1];
            float c0 = acc[2][0], c1 = acc[2][1], c2 = acc[3][0], c3 = acc[3][1];
            float m = fmaxf(fmaxf(p0, p1), fmaxf(p2, p3));
            m = fmaxf(m, __shfl_xor_sync(0xffffffffu, m, 1));
            m = fmaxf(m, __shfl_xor_sync(0xffffffffu, m, 2));
            float e0 = __expf(p0 - m), e1 = __expf(p1 - m), e2 = __expf(p2 - m), e3 = __expf(p3 - m);
            float se = e0 + e1 + e2 + e3;
            float ac = fmaf(e0, c0, fmaf(e1, c1, fmaf(e2, c2, e3 * c3)));
            se += __shfl_xor_sync(0xffffffffu, se, 1);
            ac += __shfl_xor_sync(0xffffffffu, ac, 1);
            se += __shfl_xor_sync(0xffffffffu, se, 2);
            ac += __shfl_xor_sync(0xffffffffu, ac, 2);
            if ((lane & 3) == 0 && jA < Jn) z[(size_t)b * Jn + jA] = ac / se;
        }
        {   // row B
            float p0 = acc[0][2], p1 = acc[0][3], p2 = acc[1][2], p3 = acc[1][3];
            float c0 = acc[2][2], c1 = acc[2][3], c2 = acc[3][2], c3 = acc[3][3];
            float m = fmaxf(fmaxf(p0, p1), fmaxf(p2, p3));
            m = fmaxf(m, __shfl_xor_sync(0xffffffffu, m, 1));
            m = fmaxf(m, __shfl_xor_sync(0xffffffffu, m, 2));
            float e0 = __expf(p0 - m), e1 = __expf(p1 - m), e2 = __expf(p2 - m), e3 = __expf(p3 - m);
            float se = e0 + e1 + e2 + e3;
            float ac = fmaf(e0, c0, fmaf(e1, c1, fmaf(e2, c2, e3 * c3)));
            se += __shfl_xor_sync(0xffffffffu, se, 1);
            ac += __shfl_xor_sync(0xffffffffu, ac, 1);
            se += __shfl_xor_sync(0xffffffffu, se, 2);
            ac += __shfl_xor_sync(0xffffffffu, ac, 2);
            int jB = jA + 8;
            if ((lane & 3) == 0 && jB < Jn) z[(size_t)b * Jn + jB] = ac / se;
        }

        if (bi + 1 < BPC) asm volatile("cp.async.wait_group 0;" ::: "memory");
        __syncthreads();
    }
}

// ================= launch =================
extern "C" void kernel_launch(void* const* d_in, const int* in_sizes, int n_in,
                              void* d_out, int out_size) {
    const int*   x     = (const int*)  d_in[0];
    const int*   ei    = (const int*)  d_in[1];
    const float* ew    = (const float*)d_in[2];
    const float* embed = (const float*)d_in[4];
    const float* ggc   = (const float*)d_in[5];
    const float* wih   = (const float*)d_in[6];
    const float* whh   = (const float*)d_in[7];
    const float* bih   = (const float*)d_in[8];
    const float* bhh   = (const float*)d_in[9];
    const float* W1w   = (const float*)d_in[10];
    const float* W1b   = (const float*)d_in[11];
    const float* W2w   = (const float*)d_in[12];
    const float* W2b   = (const float*)d_in[13];
    const float* Wtw   = (const float*)d_in[14];
    const float* Wtb   = (const float*)d_in[15];
    const float* qw    = (const float*)d_in[16];
    const float* qb    = (const float*)d_in[17];
    const float* W3w   = (const float*)d_in[18];
    const float* W3b   = (const float*)d_in[19];
    float* z = (float*)d_out;

    cudaFuncSetAttribute(k_ztc, cudaFuncAttributeMaxDynamicSharedMemorySize, SM_TOTAL);

    int ne = Jpad * (KE / 2);
    k_prep_e<<<(ne + 255) / 256, 256>>>(embed);
    k_wt<<<(300 * Hh + 255) / 256, 256>>>(wih, whh);
    k_gather<<<Nn, 128>>>(x, embed, ggc);
    k_scatter<<<Ej, 128>>>(ei, ew);
    k_gru2<<<Nn / 4, 416>>>(bih, bhh);
    k_attn<<<Bb, 128>>>(W1w, W1b, W2w, W2b, Wtw, Wtb, qw, qb, W3w, W3b);
    int nc = Bb * 32 * KE;
    k_prep_c<<<(nc + 255) / 256, 256>>>();
    k_ztc<<<dim3(NJT, BSPLIT), 128, SM_TOTAL>>>(z);
}

// round 7
// speedup vs baseline: 1.5548x; 1.1668x over previous
#include <cuda_runtime.h>
#include <cuda_bf16.h>
#include <math.h>
#include <stdint.h>

#define Hh 100
#define Nn 1024
#define Bb 64
#define Ll 16
#define Ej 2048
#define Jn 40000
#define Jpad 40064
#define KP 224            // packed K: [hi(112) | lo(112)]
#define RB 448            // bytes per packed row in global
#define ST 464            // smem row stride (conflict-free: 29*16B)
#define JT 128            // j rows per CTA
#define NJT (Jpad/JT)     // 313
#define SM_A (JT*ST)              // 59392
#define SM_B (128*ST)             // 59392 per buf (4 batches x 32 rows)
#define SM_TOTAL (SM_A + 2*SM_B)  // 178176

// ---------------- device scratch (no runtime allocs) ----------------
__device__ float g_h   [Nn*Hh];
__device__ float g_m   [Nn*Hh];
__device__ float g_agg [Nn*Hh];
__device__ float g_h2  [Nn*Hh];
__device__ float g_vtT [Bb*Hh*Ll];   // [b][h][l]
__device__ float g_vT  [Bb*Hh*Ll];   // [b][h][l]
__device__ float g_sh  [Bb*Hh];
__device__ float g_wihT[Hh*300];
__device__ float g_whhT[Hh*300];
__device__ __align__(16) __nv_bfloat16 g_epk[(size_t)Jpad*KP];     // [j][hi|lo]
__device__ __align__(16) __nv_bfloat16 g_cpk[(size_t)Bb*32*KP];    // [b][32][hi|lo]

__device__ __forceinline__ float sigm(float x) { return 1.0f / (1.0f + __expf(-x)); }

__device__ __forceinline__ uint32_t smem_u32(const void* p) {
    uint32_t a;
    asm("{ .reg .u64 t; cvta.to.shared.u64 t, %1; cvt.u32.u64 %0, t; }" : "=r"(a) : "l"(p));
    return a;
}
__device__ __forceinline__ void cp16(uint32_t dst, const void* src) {
    asm volatile("cp.async.cg.shared.global [%0], [%1], 16;" :: "r"(dst), "l"(src) : "memory");
}
__device__ __forceinline__ void ldsm_x4(uint32_t* r, uint32_t addr) {
    asm volatile("ldmatrix.sync.aligned.m8n8.x4.shared.b16 {%0,%1,%2,%3}, [%4];"
                 : "=r"(r[0]), "=r"(r[1]), "=r"(r[2]), "=r"(r[3]) : "r"(addr));
}
__device__ __forceinline__ void ldsm_x2(uint32_t* r, uint32_t addr) {
    asm volatile("ldmatrix.sync.aligned.m8n8.x2.shared.b16 {%0,%1}, [%2];"
                 : "=r"(r[0]), "=r"(r[1]) : "r"(addr));
}
__device__ __forceinline__ void mma16816(float* d, const uint32_t* a, const uint32_t* b) {
    asm volatile(
        "mma.sync.aligned.m16n8k16.row.col.f32.bf16.bf16.f32 "
        "{%0,%1,%2,%3}, {%4,%5,%6,%7}, {%8,%9}, {%0,%1,%2,%3};"
        : "+f"(d[0]), "+f"(d[1]), "+f"(d[2]), "+f"(d[3])
        : "r"(a[0]), "r"(a[1]), "r"(a[2]), "r"(a[3]), "r"(b[0]), "r"(b[1]));
}

// ================= K_prep_e: embed -> packed [hi|lo] bf16 rows =================
__global__ void k_prep_e(const float* __restrict__ embed) {
    int idx = blockIdx.x * 256 + threadIdx.x;     // pairs
    if (idx >= Jpad * (KP/2)) return;
    int j  = idx / (KP/2);
    int kp = (idx - j * (KP/2)) * 2;
    __nv_bfloat16 o[2];
    #pragma unroll
    for (int i = 0; i < 2; i++) {
        int k = kp + i;
        int lo = k >= 112;
        int h = k - lo * 112;
        float v = (j < Jn && h < Hh) ? embed[(size_t)j * Hh + h] : 0.0f;
        __nv_bfloat16 hi = __float2bfloat16(v);
        o[i] = lo ? __float2bfloat16(v - __bfloat162float(hi)) : hi;
    }
    *(uint32_t*)(g_epk + (size_t)j * KP + kp) = *(uint32_t*)o;
}

// ================= K_prep_c: coef rows (vt, v+sh) packed [hi|lo] =================
__global__ void k_prep_c() {
    int idx = blockIdx.x * 256 + threadIdx.x;
    if (idx >= Bb * 32 * KP) return;
    int k = idx % KP;
    int r = (idx / KP) & 31;
    int b = idx / (KP * 32);
    int lo = k >= 112;
    int h = k - lo * 112;
    float v = 0.0f;
    if (h < Hh) {
        if (r < 16) v = g_vtT[b * Hh * Ll + h * Ll + r];
        else        v = g_vT [b * Hh * Ll + h * Ll + (r - 16)] + g_sh[b * Hh + h];
    }
    __nv_bfloat16 hi = __float2bfloat16(v);
    g_cpk[idx] = lo ? __float2bfloat16(v - __bfloat162float(hi)) : hi;
}

// ================= K_wt: transpose GRU weights =================
__global__ void k_wt(const float* __restrict__ wih, const float* __restrict__ whh) {
    int i = blockIdx.x * 256 + threadIdx.x;
    if (i < 300 * Hh) {
        int r = i / Hh, c = i % Hh;
        g_wihT[c * 300 + r] = wih[i];
        g_whhT[c * 300 + r] = whh[i];
    }
}

// ================= K1: gather + m = h @ ggc_w =================
__global__ void k_gather(const int* __restrict__ x, const float* __restrict__ embed,
                         const float* __restrict__ ggc) {
    __shared__ float hs[Hh];
    int i = blockIdx.x, t = threadIdx.x;
    if (t < Hh) {
        float v = embed[(size_t)x[i] * Hh + t];
        hs[t] = v;
        g_h[i * Hh + t] = v;
        g_agg[i * Hh + t] = 0.0f;
    }
    __syncthreads();
    if (t < Hh) {
        float acc = 0.0f;
        #pragma unroll 4
        for (int c = 0; c < Hh; c++) acc = fmaf(hs[c], ggc[c * Hh + t], acc);
        g_m[i * Hh + t] = acc;
    }
}

// ================= K2: scatter-add =================
__global__ void k_scatter(const int* __restrict__ ei, const float* __restrict__ ew) {
    int e = blockIdx.x, t = threadIdx.x;
    if (t < Hh) {
        int s = ei[e], d = ei[Ej + e];
        atomicAdd(&g_agg[d * Hh + t], ew[e] * g_m[s * Hh + t]);
    }
}

// ================= K3: GRU =================
__global__ void k_gru2(const float* __restrict__ bih, const float* __restrict__ bhh) {
    __shared__ float a_s[4][Hh], h_s[4][Hh];
    __shared__ float gi_s[4][300], gh_s[4][300];
    int nb = blockIdx.x * 4;
    int t = threadIdx.x;             // block 416
    for (int i = t; i < 4 * Hh; i += 416) {
        int n = i / Hh, c = i % Hh;
        a_s[n][c] = g_agg[(nb + n) * Hh + c];
        h_s[n][c] = g_h  [(nb + n) * Hh + c];
    }
    __syncthreads();
    if (t < 300) {
        float ai0 = bih[t], ai1 = ai0, ai2 = ai0, ai3 = ai0;
        float ah0 = bhh[t], ah1 = ah0, ah2 = ah0, ah3 = ah0;
        #pragma unroll 4
        for (int c = 0; c < Hh; c++) {
            float wv = g_wihT[c * 300 + t];
            float uv = g_whhT[c * 300 + t];
            ai0 = fmaf(a_s[0][c], wv, ai0); ah0 = fmaf(h_s[0][c], uv, ah0);
            ai1 = fmaf(a_s[1][c], wv, ai1); ah1 = fmaf(h_s[1][c], uv, ah1);
            ai2 = fmaf(a_s[2][c], wv, ai2); ah2 = fmaf(h_s[2][c], uv, ah2);
            ai3 = fmaf(a_s[3][c], wv, ai3); ah3 = fmaf(h_s[3][c], uv, ah3);
        }
        gi_s[0][t] = ai0; gi_s[1][t] = ai1; gi_s[2][t] = ai2; gi_s[3][t] = ai3;
        gh_s[0][t] = ah0; gh_s[1][t] = ah1; gh_s[2][t] = ah2; gh_s[3][t] = ah3;
    }
    __syncthreads();
    if (t < 400) {
        int n = t / Hh, k = t % Hh;
        float r  = sigm(gi_s[n][k]         + gh_s[n][k]);
        float zg = sigm(gi_s[n][Hh + k]    + gh_s[n][Hh + k]);
        float ng = tanhf(gi_s[n][2*Hh + k] + r * gh_s[n][2*Hh + k]);
        g_h2[(nb + n) * Hh + k] = (1.0f - zg) * ng + zg * h_s[n][k];
    }
}

// ================= K4: attention readout =================
__global__ void k_attn(const float* __restrict__ W1w, const float* __restrict__ W1b,
                       const float* __restrict__ W2w, const float* __restrict__ W2b,
                       const float* __restrict__ Wtw, const float* __restrict__ Wtb,
                       const float* __restrict__ qw,  const float* __restrict__ qb,
                       const float* __restrict__ W3w, const float* __restrict__ W3b) {
    __shared__ float vs[Ll * Hh];
    __shared__ float t1[Hh];
    __shared__ float a_s[Ll * Hh];
    __shared__ float alpha_s[Ll];
    __shared__ float sg[Hh];
    int b = blockIdx.x, t = threadIdx.x;

    for (int i = t; i < Ll * Hh; i += 128) vs[i] = g_h2[b * Ll * Hh + i];
    __syncthreads();

    if (t < Hh) {
        float acc = W1b[t];
        const float* w = W1w + t * Hh;
        #pragma unroll 4
        for (int c = 0; c < Hh; c++) acc = fmaf(vs[15 * Hh + c], w[c], acc);
        t1[t] = acc;
    }
    __syncthreads();

    for (int idx = t; idx < Ll * Hh; idx += 128) {
        int l = idx / Hh, k = idx % Hh;
        float acc = W2b[k];
        const float* w = W2w + k * Hh;
        const float* vrow = vs + l * Hh;
        #pragma unroll 4
        for (int c = 0; c < Hh; c++) acc = fmaf(vrow[c], w[c], acc);
        a_s[idx] = sigm(t1[k] + acc);
    }
    __syncthreads();

    if (t < Ll) {
        float acc = qb[0];
        #pragma unroll 4
        for (int k = 0; k < Hh; k++) acc = fmaf(a_s[t * Hh + k], qw[k], acc);
        alpha_s[t] = acc;
    }
    __syncthreads();

    if (t < Hh) {
        float acc = 0.0f;
        #pragma unroll
        for (int l = 0; l < Ll; l++) acc = fmaf(alpha_s[l], vs[l * Hh + t], acc);
        sg[t] = acc;
    }
    __syncthreads();

    if (t < Hh) {
        float acc = W3b[t];
        const float* w = W3w + t * 2 * Hh;
        #pragma unroll 4
        for (int c = 0; c < Hh; c++)
            acc = fmaf(vs[15 * Hh + c], w[c], fmaf(sg[c], w[Hh + c], acc));
        g_sh[b * Hh + t] = acc;
    }

    for (int idx = t; idx < Ll * Hh; idx += 128) {
        int l = idx / Hh, k = idx % Hh;
        float acc = Wtb[k];
        const float* w = Wtw + k * Hh;
        const float* vrow = vs + l * Hh;
        #pragma unroll 4
        for (int c = 0; c < Hh; c++) acc = fmaf(vrow[c], w[c], acc);
        g_vtT[b * Hh * Ll + k * Ll + l] = acc;
        g_vT [b * Hh * Ll + k * Ll + l] = vs[l * Hh + k];
    }
}

// ================= K5: HMMA fused GEMM + softmax epilogue =================
// CTA: 128 j-rows x 16 batches (4 bt-iters of 4 b). Warp grid 4x2: m32 x n64.
// 3-term product from single hi/lo loads: hi*hi + lo*hi + hi*lo.
__global__ void __launch_bounds__(256, 1) k_ztc(float* __restrict__ z) {
    extern __shared__ __align__(128) char sm[];
    const uint32_t smA = smem_u32(sm);
    const uint32_t smB = smA + SM_A;
    int tid = threadIdx.x, warp = tid >> 5, lane = tid & 31;
    int wr = warp >> 1, wc = warp & 1;
    int jt = blockIdx.x, bs = blockIdx.y;      // bs: 0..3, 16 batches each

    // load A tile (128 rows x 448B)
    {
        const char* src = (const char*)g_epk + (size_t)jt * JT * RB;
        for (int i = tid; i < JT * 28; i += 256) {
            int r = i / 28, c = i - r * 28;
            cp16(smA + (uint32_t)r * ST + c * 16, src + (size_t)r * RB + c * 16);
        }
    }
    // load B for bt=0 (4 batches x 32 rows)
    {
        const char* src = (const char*)g_cpk + (size_t)(bs * 16) * 32 * RB;
        for (int i = tid; i < 128 * 28; i += 256) {
            int r = i / 28, c = i - r * 28;
            cp16(smB + (uint32_t)r * ST + c * 16, src + (size_t)r * RB + c * 16);
        }
    }
    asm volatile("cp.async.commit_group;" ::: "memory");
    asm volatile("cp.async.wait_group 0;" ::: "memory");
    __syncthreads();

    const uint32_t aBase = smA + (uint32_t)(wr * 32 + (lane & 15)) * ST + ((lane >> 4) << 4);
    const uint32_t bOff  = (uint32_t)(wc * 64 + (lane & 7)) * ST + (((lane >> 3) & 1) << 4);

    #pragma unroll 1
    for (int bt = 0; bt < 4; bt++) {
        if (bt + 1 < 4) {
            const char* src = (const char*)g_cpk + (size_t)(bs * 16 + (bt + 1) * 4) * 32 * RB;
            uint32_t dst = smB + (uint32_t)((bt + 1) & 1) * SM_B;
            for (int i = tid; i < 128 * 28; i += 256) {
                int r = i / 28, c = i - r * 28;
                cp16(dst + (uint32_t)r * ST + c * 16, src + (size_t)r * RB + c * 16);
            }
            asm volatile("cp.async.commit_group;" ::: "memory");
        }
        const uint32_t bBase = smB + (uint32_t)(bt & 1) * SM_B + bOff;

        float acc[2][8][4];
        #pragma unroll
        for (int mt = 0; mt < 2; mt++)
            #pragma unroll
            for (int nt = 0; nt < 8; nt++)
                #pragma unroll
                for (int q = 0; q < 4; q++) acc[mt][nt][q] = 0.0f;

        #pragma unroll
        for (int ksi = 0; ksi < 7; ksi++) {
            uint32_t ah[2][4], al[2][4];
            #pragma unroll
            for (int mt = 0; mt < 2; mt++) {
                ldsm_x4(ah[mt], aBase + (uint32_t)mt * (16 * ST) + ksi * 32);
                ldsm_x4(al[mt], aBase + (uint32_t)mt * (16 * ST) + 224 + ksi * 32);
            }
            #pragma unroll
            for (int nt = 0; nt < 8; nt++) {
                uint32_t bh[2], bl[2];
                ldsm_x2(bh, bBase + (uint32_t)nt * (8 * ST) + ksi * 32);
                ldsm_x2(bl, bBase + (uint32_t)nt * (8 * ST) + 224 + ksi * 32);
                #pragma unroll
                for (int mt = 0; mt < 2; mt++) {
                    mma16816(acc[mt][nt], ah[mt], bh);
                    mma16816(acc[mt][nt], al[mt], bh);
                    mma16816(acc[mt][nt], ah[mt], bl);
                }
            }
        }

        // epilogue: per (mt, bpair): p = nt {0,1}, c = nt {2,3} within the 4-nt group
        #pragma unroll
        for (int mt = 0; mt < 2; mt++) {
            #pragma unroll
            for (int bp = 0; bp < 2; bp++) {
                int nb = bp * 4;
                int b = bs * 16 + bt * 4 + wc * 2 + bp;
                int jA = jt * JT + wr * 32 + mt * 16 + (lane >> 2);
                #pragma unroll
                for (int half = 0; half < 2; half++) {   // 0: row jA, 1: row jA+8
                    int q0 = half * 2, q1 = half * 2 + 1;
                    float p0 = acc[mt][nb + 0][q0], p1 = acc[mt][nb + 0][q1];
                    float p2 = acc[mt][nb + 1][q0], p3 = acc[mt][nb + 1][q1];
                    float c0 = acc[mt][nb + 2][q0], c1 = acc[mt][nb + 2][q1];
                    float c2 = acc[mt][nb + 3][q0], c3 = acc[mt][nb + 3][q1];
                    float m = fmaxf(fmaxf(p0, p1), fmaxf(p2, p3));
                    m = fmaxf(m, __shfl_xor_sync(0xffffffffu, m, 1));
                    m = fmaxf(m, __shfl_xor_sync(0xffffffffu, m, 2));
                    float e0 = __expf(p0 - m), e1 = __expf(p1 - m);
                    float e2 = __expf(p2 - m), e3 = __expf(p3 - m);
                    float se = e0 + e1 + e2 + e3;
                    float ac = fmaf(e0, c0, fmaf(e1, c1, fmaf(e2, c2, e3 * c3)));
                    se += __shfl_xor_sync(0xffffffffu, se, 1);
                    ac += __shfl_xor_sync(0xffffffffu, ac, 1);
                    se += __shfl_xor_sync(0xffffffffu, se, 2);
                    ac += __shfl_xor_sync(0xffffffffu, ac, 2);
                    int j = jA + half * 8;
                    if ((lane & 3) == 0 && j < Jn)
                        z[(size_t)b * Jn + j] = ac / se;
                }
            }
        }

        if (bt + 1 < 4) asm volatile("cp.async.wait_group 0;" ::: "memory");
        __syncthreads();
    }
}

// ================= launch =================
extern "C" void kernel_launch(void* const* d_in, const int* in_sizes, int n_in,
                              void* d_out, int out_size) {
    const int*   x     = (const int*)  d_in[0];
    const int*   ei    = (const int*)  d_in[1];
    const float* ew    = (const float*)d_in[2];
    const float* embed = (const float*)d_in[4];
    const float* ggc   = (const float*)d_in[5];
    const float* wih   = (const float*)d_in[6];
    const float* whh   = (const float*)d_in[7];
    const float* bih   = (const float*)d_in[8];
    const float* bhh   = (const float*)d_in[9];
    const float* W1w   = (const float*)d_in[10];
    const float* W1b   = (const float*)d_in[11];
    const float* W2w   = (const float*)d_in[12];
    const float* W2b   = (const float*)d_in[13];
    const float* Wtw   = (const float*)d_in[14];
    const float* Wtb   = (const float*)d_in[15];
    const float* qw    = (const float*)d_in[16];
    const float* qb    = (const float*)d_in[17];
    const float* W3w   = (const float*)d_in[18];
    const float* W3b   = (const float*)d_in[19];
    float* z = (float*)d_out;

    cudaFuncSetAttribute(k_ztc, cudaFuncAttributeMaxDynamicSharedMemorySize, SM_TOTAL);

    int ne = Jpad * (KP / 2);
    k_prep_e<<<(ne + 255) / 256, 256>>>(embed);
    k_wt<<<(300 * Hh + 255) / 256, 256>>>(wih, whh);
    k_gather<<<Nn, 128>>>(x, embed, ggc);
    k_scatter<<<Ej, 128>>>(ei, ew);
    k_gru2<<<Nn / 4, 416>>>(bih, bhh);
    k_attn<<<Bb, 128>>>(W1w, W1b, W2w, W2b, Wtw, Wtb, qw, qb, W3w, W3b);
    int nc = Bb * 32 * KP;
    k_prep_c<<<(nc + 255) / 256, 256>>>();
    k_ztc<<<dim3(NJT, 4), 256, SM_TOTAL>>>(z);
}

// round 8
// speedup vs baseline: 1.7681x; 1.1372x over previous
#include <cuda_runtime.h>
#include <cuda_fp16.h>
#include <math.h>
#include <stdint.h>

#define Hh 100
#define Nn 1024
#define Bb 64
#define Ll 16
#define Ej 2048
#define Jn 40000
#define Jpad 40064
#define KP 224            // A packed K: [e_hi(112) | e_lo(112)] fp16
#define RB 448            // bytes per packed A row in global
#define ST 464            // A smem row stride (conflict-free)
#define KPB 112           // B packed K: c_hi only
#define RBB 224           // bytes per packed B row in global
#define STB 240           // B smem row stride (conflict-free: 15*16)
#define JT 128            // j rows per CTA
#define NJT (Jpad/JT)     // 313
#define SM_A (JT*ST)               // 59392
#define SM_B (128*STB)             // 30720 per buf (4 batches x 32 rows)
#define SM_TOTAL (SM_A + 2*SM_B)   // 120832

// ---------------- device scratch (no runtime allocs) ----------------
__device__ float g_h   [Nn*Hh];
__device__ float g_m   [Nn*Hh];
__device__ float g_agg [Nn*Hh];
__device__ float g_h2  [Nn*Hh];
__device__ float g_vtT [Bb*Hh*Ll];   // [b][h][l]
__device__ float g_vT  [Bb*Hh*Ll];   // [b][h][l]
__device__ float g_sh  [Bb*Hh];
__device__ float g_wihT[Hh*300];
__device__ float g_whhT[Hh*300];
__device__ __align__(16) __half g_epk[(size_t)Jpad*KP];     // [j][hi|lo]
__device__ __align__(16) __half g_cpk[(size_t)Bb*32*KPB];   // [b][32][hi]

__device__ __forceinline__ float sigm(float x) { return 1.0f / (1.0f + __expf(-x)); }

__device__ __forceinline__ uint32_t smem_u32(const void* p) {
    uint32_t a;
    asm("{ .reg .u64 t; cvta.to.shared.u64 t, %1; cvt.u32.u64 %0, t; }" : "=r"(a) : "l"(p));
    return a;
}
__device__ __forceinline__ void cp16(uint32_t dst, const void* src) {
    asm volatile("cp.async.cg.shared.global [%0], [%1], 16;" :: "r"(dst), "l"(src) : "memory");
}
__device__ __forceinline__ void ldsm_x4(uint32_t* r, uint32_t addr) {
    asm volatile("ldmatrix.sync.aligned.m8n8.x4.shared.b16 {%0,%1,%2,%3}, [%4];"
                 : "=r"(r[0]), "=r"(r[1]), "=r"(r[2]), "=r"(r[3]) : "r"(addr));
}
__device__ __forceinline__ void ldsm_x2(uint32_t* r, uint32_t addr) {
    asm volatile("ldmatrix.sync.aligned.m8n8.x2.shared.b16 {%0,%1}, [%2];"
                 : "=r"(r[0]), "=r"(r[1]) : "r"(addr));
}
__device__ __forceinline__ void mma16816(float* d, const uint32_t* a, const uint32_t* b) {
    asm volatile(
        "mma.sync.aligned.m16n8k16.row.col.f32.f16.f16.f32 "
        "{%0,%1,%2,%3}, {%4,%5,%6,%7}, {%8,%9}, {%0,%1,%2,%3};"
        : "+f"(d[0]), "+f"(d[1]), "+f"(d[2]), "+f"(d[3])
        : "r"(a[0]), "r"(a[1]), "r"(a[2]), "r"(a[3]), "r"(b[0]), "r"(b[1]));
}

// ================= K_prep_e: embed -> packed [hi|lo] fp16 rows =================
__global__ void k_prep_e(const float* __restrict__ embed) {
    int idx = blockIdx.x * 256 + threadIdx.x;     // pairs
    if (idx >= Jpad * (KP/2)) return;
    int j  = idx / (KP/2);
    int kp = (idx - j * (KP/2)) * 2;
    __half o[2];
    #pragma unroll
    for (int i = 0; i < 2; i++) {
        int k = kp + i;
        int lo = k >= 112;
        int h = k - lo * 112;
        float v = (j < Jn && h < Hh) ? embed[(size_t)j * Hh + h] : 0.0f;
        __half hi = __float2half(v);
        o[i] = lo ? __float2half(v - __half2float(hi)) : hi;
    }
    *(uint32_t*)(g_epk + (size_t)j * KP + kp) = *(uint32_t*)o;
}

// ================= K_prep_c: coef rows (vt, v+sh) fp16 =================
__global__ void k_prep_c() {
    int idx = blockIdx.x * 256 + threadIdx.x;
    if (idx >= Bb * 32 * KPB) return;
    int h = idx % KPB;
    int r = (idx / KPB) & 31;
    int b = idx / (KPB * 32);
    float v = 0.0f;
    if (h < Hh) {
        if (r < 16) v = g_vtT[b * Hh * Ll + h * Ll + r];
        else        v = g_vT [b * Hh * Ll + h * Ll + (r - 16)] + g_sh[b * Hh + h];
    }
    g_cpk[idx] = __float2half(v);
}

// ================= K_wt: transpose GRU weights =================
__global__ void k_wt(const float* __restrict__ wih, const float* __restrict__ whh) {
    int i = blockIdx.x * 256 + threadIdx.x;
    if (i < 300 * Hh) {
        int r = i / Hh, c = i % Hh;
        g_wihT[c * 300 + r] = wih[i];
        g_whhT[c * 300 + r] = whh[i];
    }
}

// ================= K1: gather + m = h @ ggc_w =================
__global__ void k_gather(const int* __restrict__ x, const float* __restrict__ embed,
                         const float* __restrict__ ggc) {
    __shared__ float hs[Hh];
    int i = blockIdx.x, t = threadIdx.x;
    if (t < Hh) {
        float v = embed[(size_t)x[i] * Hh + t];
        hs[t] = v;
        g_h[i * Hh + t] = v;
        g_agg[i * Hh + t] = 0.0f;
    }
    __syncthreads();
    if (t < Hh) {
        float acc = 0.0f;
        #pragma unroll 4
        for (int c = 0; c < Hh; c++) acc = fmaf(hs[c], ggc[c * Hh + t], acc);
        g_m[i * Hh + t] = acc;
    }
}

// ================= K2: scatter-add =================
__global__ void k_scatter(const int* __restrict__ ei, const float* __restrict__ ew) {
    int e = blockIdx.x, t = threadIdx.x;
    if (t < Hh) {
        int s = ei[e], d = ei[Ej + e];
        atomicAdd(&g_agg[d * Hh + t], ew[e] * g_m[s * Hh + t]);
    }
}

// ================= K3: GRU =================
__global__ void k_gru2(const float* __restrict__ bih, const float* __restrict__ bhh) {
    __shared__ float a_s[4][Hh], h_s[4][Hh];
    __shared__ float gi_s[4][300], gh_s[4][300];
    int nb = blockIdx.x * 4;
    int t = threadIdx.x;             // block 416
    for (int i = t; i < 4 * Hh; i += 416) {
        int n = i / Hh, c = i % Hh;
        a_s[n][c] = g_agg[(nb + n) * Hh + c];
        h_s[n][c] = g_h  [(nb + n) * Hh + c];
    }
    __syncthreads();
    if (t < 300) {
        float ai0 = bih[t], ai1 = ai0, ai2 = ai0, ai3 = ai0;
        float ah0 = bhh[t], ah1 = ah0, ah2 = ah0, ah3 = ah0;
        #pragma unroll 4
        for (int c = 0; c < Hh; c++) {
            float wv = g_wihT[c * 300 + t];
            float uv = g_whhT[c * 300 + t];
            ai0 = fmaf(a_s[0][c], wv, ai0); ah0 = fmaf(h_s[0][c], uv, ah0);
            ai1 = fmaf(a_s[1][c], wv, ai1); ah1 = fmaf(h_s[1][c], uv, ah1);
            ai2 = fmaf(a_s[2][c], wv, ai2); ah2 = fmaf(h_s[2][c], uv, ah2);
            ai3 = fmaf(a_s[3][c], wv, ai3); ah3 = fmaf(h_s[3][c], uv, ah3);
        }
        gi_s[0][t] = ai0; gi_s[1][t] = ai1; gi_s[2][t] = ai2; gi_s[3][t] = ai3;
        gh_s[0][t] = ah0; gh_s[1][t] = ah1; gh_s[2][t] = ah2; gh_s[3][t] = ah3;
    }
    __syncthreads();
    if (t < 400) {
        int n = t / Hh, k = t % Hh;
        float r  = sigm(gi_s[n][k]         + gh_s[n][k]);
        float zg = sigm(gi_s[n][Hh + k]    + gh_s[n][Hh + k]);
        float ng = tanhf(gi_s[n][2*Hh + k] + r * gh_s[n][2*Hh + k]);
        g_h2[(nb + n) * Hh + k] = (1.0f - zg) * ng + zg * h_s[n][k];
    }
}

// ================= K4: attention readout =================
__global__ void k_attn(const float* __restrict__ W1w, const float* __restrict__ W1b,
                       const float* __restrict__ W2w, const float* __restrict__ W2b,
                       const float* __restrict__ Wtw, const float* __restrict__ Wtb,
                       const float* __restrict__ qw,  const float* __restrict__ qb,
                       const float* __restrict__ W3w, const float* __restrict__ W3b) {
    __shared__ float vs[Ll * Hh];
    __shared__ float t1[Hh];
    __shared__ float a_s[Ll * Hh];
    __shared__ float alpha_s[Ll];
    __shared__ float sg[Hh];
    int b = blockIdx.x, t = threadIdx.x;

    for (int i = t; i < Ll * Hh; i += 128) vs[i] = g_h2[b * Ll * Hh + i];
    __syncthreads();

    if (t < Hh) {
        float acc = W1b[t];
        const float* w = W1w + t * Hh;
        #pragma unroll 4
        for (int c = 0; c < Hh; c++) acc = fmaf(vs[15 * Hh + c], w[c], acc);
        t1[t] = acc;
    }
    __syncthreads();

    for (int idx = t; idx < Ll * Hh; idx += 128) {
        int l = idx / Hh, k = idx % Hh;
        float acc = W2b[k];
        const float* w = W2w + k * Hh;
        const float* vrow = vs + l * Hh;
        #pragma unroll 4
        for (int c = 0; c < Hh; c++) acc = fmaf(vrow[c], w[c], acc);
        a_s[idx] = sigm(t1[k] + acc);
    }
    __syncthreads();

    if (t < Ll) {
        float acc = qb[0];
        #pragma unroll 4
        for (int k = 0; k < Hh; k++) acc = fmaf(a_s[t * Hh + k], qw[k], acc);
        alpha_s[t] = acc;
    }
    __syncthreads();

    if (t < Hh) {
        float acc = 0.0f;
        #pragma unroll
        for (int l = 0; l < Ll; l++) acc = fmaf(alpha_s[l], vs[l * Hh + t], acc);
        sg[t] = acc;
    }
    __syncthreads();

    if (t < Hh) {
        float acc = W3b[t];
        const float* w = W3w + t * 2 * Hh;
        #pragma unroll 4
        for (int c = 0; c < Hh; c++)
            acc = fmaf(vs[15 * Hh + c], w[c], fmaf(sg[c], w[Hh + c], acc));
        g_sh[b * Hh + t] = acc;
    }

    for (int idx = t; idx < Ll * Hh; idx += 128) {
        int l = idx / Hh, k = idx % Hh;
        float acc = Wtb[k];
        const float* w = Wtw + k * Hh;
        const float* vrow = vs + l * Hh;
        #pragma unroll 4
        for (int c = 0; c < Hh; c++) acc = fmaf(vrow[c], w[c], acc);
        g_vtT[b * Hh * Ll + k * Ll + l] = acc;
        g_vT [b * Hh * Ll + k * Ll + l] = vs[l * Hh + k];
    }
}

// ================= K5: HMMA fused GEMM + softmax epilogue =================
// A = [e_hi | e_lo] fp16 (K=224), B = c_hi fp16 (K=112).
// D = e_hi.c + e_lo.c : B fragment reused for both A halves (2 MMAs per pair).
__global__ void __launch_bounds__(256, 1) k_ztc(float* __restrict__ z) {
    extern __shared__ __align__(128) char sm[];
    const uint32_t smA = smem_u32(sm);
    const uint32_t smB = smA + SM_A;
    int tid = threadIdx.x, warp = tid >> 5, lane = tid & 31;
    int wr = warp >> 1, wc = warp & 1;
    int jt = blockIdx.x, bs = blockIdx.y;      // bs: 0..3, 16 batches each

    // load A tile (128 rows x 448B)
    {
        const char* src = (const char*)g_epk + (size_t)jt * JT * RB;
        for (int i = tid; i < JT * 28; i += 256) {
            int r = i / 28, c = i - r * 28;
            cp16(smA + (uint32_t)r * ST + c * 16, src + (size_t)r * RB + c * 16);
        }
    }
    // load B for bt=0 (4 batches x 32 rows x 224B)
    {
        const char* src = (const char*)g_cpk + (size_t)(bs * 16) * 32 * RBB;
        for (int i = tid; i < 128 * 14; i += 256) {
            int r = i / 14, c = i - r * 14;
            cp16(smB + (uint32_t)r * STB + c * 16, src + (size_t)r * RBB + c * 16);
        }
    }
    asm volatile("cp.async.commit_group;" ::: "memory");
    asm volatile("cp.async.wait_group 0;" ::: "memory");
    __syncthreads();

    const uint32_t aBase = smA + (uint32_t)(wr * 32 + (lane & 15)) * ST + ((lane >> 4) << 4);
    const uint32_t bOff  = (uint32_t)(wc * 64 + (lane & 7)) * STB + (((lane >> 3) & 1) << 4);

    #pragma unroll 1
    for (int bt = 0; bt < 4; bt++) {
        if (bt + 1 < 4) {
            const char* src = (const char*)g_cpk + (size_t)(bs * 16 + (bt + 1) * 4) * 32 * RBB;
            uint32_t dst = smB + (uint32_t)((bt + 1) & 1) * SM_B;
            for (int i = tid; i < 128 * 14; i += 256) {
                int r = i / 14, c = i - r * 14;
                cp16(dst + (uint32_t)r * STB + c * 16, src + (size_t)r * RBB + c * 16);
            }
            asm volatile("cp.async.commit_group;" ::: "memory");
        }
        const uint32_t bBase = smB + (uint32_t)(bt & 1) * SM_B + bOff;

        float acc[2][8][4];
        #pragma unroll
        for (int mt = 0; mt < 2; mt++)
            #pragma unroll
            for (int nt = 0; nt < 8; nt++)
                #pragma unroll
                for (int q = 0; q < 4; q++) acc[mt][nt][q] = 0.0f;

        #pragma unroll
        for (int ksi = 0; ksi < 7; ksi++) {
            uint32_t ah[2][4], al[2][4];
            #pragma unroll
            for (int mt = 0; mt < 2; mt++) {
                ldsm_x4(ah[mt], aBase + (uint32_t)mt * (16 * ST) + ksi * 32);
                ldsm_x4(al[mt], aBase + (uint32_t)mt * (16 * ST) + 224 + ksi * 32);
            }
            #pragma unroll
            for (int nt = 0; nt < 8; nt++) {
                uint32_t bh[2];
                ldsm_x2(bh, bBase + (uint32_t)nt * (8 * STB) + ksi * 32);
                #pragma unroll
                for (int mt = 0; mt < 2; mt++) {
                    mma16816(acc[mt][nt], ah[mt], bh);
                    mma16816(acc[mt][nt], al[mt], bh);
                }
            }
        }

        // epilogue: per (mt, bpair): p = nt {0,1}, c = nt {2,3} within the 4-nt group
        #pragma unroll
        for (int mt = 0; mt < 2; mt++) {
            #pragma unroll
            for (int bp = 0; bp < 2; bp++) {
                int nb = bp * 4;
                int b = bs * 16 + bt * 4 + wc * 2 + bp;
                int jA = jt * JT + wr * 32 + mt * 16 + (lane >> 2);
                #pragma unroll
                for (int half = 0; half < 2; half++) {   // 0: row jA, 1: row jA+8
                    int q0 = half * 2, q1 = half * 2 + 1;
                    float p0 = acc[mt][nb + 0][q0], p1 = acc[mt][nb + 0][q1];
                    float p2 = acc[mt][nb + 1][q0], p3 = acc[mt][nb + 1][q1];
                    float c0 = acc[mt][nb + 2][q0], c1 = acc[mt][nb + 2][q1];
                    float c2 = acc[mt][nb + 3][q0], c3 = acc[mt][nb + 3][q1];
                    float m = fmaxf(fmaxf(p0, p1), fmaxf(p2, p3));
                    m = fmaxf(m, __shfl_xor_sync(0xffffffffu, m, 1));
                    m = fmaxf(m, __shfl_xor_sync(0xffffffffu, m, 2));
                    float e0 = __expf(p0 - m), e1 = __expf(p1 - m);
                    float e2 = __expf(p2 - m), e3 = __expf(p3 - m);
                    float se = e0 + e1 + e2 + e3;
                    float ac = fmaf(e0, c0, fmaf(e1, c1, fmaf(e2, c2, e3 * c3)));
                    se += __shfl_xor_sync(0xffffffffu, se, 1);
                    ac += __shfl_xor_sync(0xffffffffu, ac, 1);
                    se += __shfl_xor_sync(0xffffffffu, se, 2);
                    ac += __shfl_xor_sync(0xffffffffu, ac, 2);
                    int j = jA + half * 8;
                    if ((lane & 3) == 0 && j < Jn)
                        z[(size_t)b * Jn + j] = ac / se;
                }
            }
        }

        if (bt + 1 < 4) asm volatile("cp.async.wait_group 0;" ::: "memory");
        __syncthreads();
    }
}

// ================= launch =================
extern "C" void kernel_launch(void* const* d_in, const int* in_sizes, int n_in,
                              void* d_out, int out_size) {
    const int*   x     = (const int*)  d_in[0];
    const int*   ei    = (const int*)  d_in[1];
    const float* ew    = (const float*)d_in[2];
    const float* embed = (const float*)d_in[4];
    const float* ggc   = (const float*)d_in[5];
    const float* wih   = (const float*)d_in[6];
    const float* whh   = (const float*)d_in[7];
    const float* bih   = (const float*)d_in[8];
    const float* bhh   = (const float*)d_in[9];
    const float* W1w   = (const float*)d_in[10];
    const float* W1b   = (const float*)d_in[11];
    const float* W2w   = (const float*)d_in[12];
    const float* W2b   = (const float*)d_in[13];
    const float* Wtw   = (const float*)d_in[14];
    const float* Wtb   = (const float*)d_in[15];
    const float* qw    = (const float*)d_in[16];
    const float* qb    = (const float*)d_in[17];
    const float* W3w   = (const float*)d_in[18];
    const float* W3b   = (const float*)d_in[19];
    float* z = (float*)d_out;

    cudaFuncSetAttribute(k_ztc, cudaFuncAttributeMaxDynamicSharedMemorySize, SM_TOTAL);

    int ne = Jpad * (KP / 2);
    k_prep_e<<<(ne + 255) / 256, 256>>>(embed);
    k_wt<<<(300 * Hh + 255) / 256, 256>>>(wih, whh);
    k_gather<<<Nn, 128>>>(x, embed, ggc);
    k_scatter<<<Ej, 128>>>(ei, ew);
    k_gru2<<<Nn / 4, 416>>>(bih, bhh);
    k_attn<<<Bb, 128>>>(W1w, W1b, W2w, W2b, Wtw, Wtb, qw, qb, W3w, W3b);
    int nc = Bb * 32 * KPB;
    k_prep_c<<<(nc + 255) / 256, 256>>>();
    k_ztc<<<dim3(NJT, 4), 256, SM_TOTAL>>>(z);
}

// round 9
// speedup vs baseline: 2.2028x; 1.2459x over previous
#include <cuda_runtime.h>
#include <cuda_fp16.h>
#include <math.h>
#include <stdint.h>

#define Hh 100
#define Nn 1024
#define Bb 64
#define Ll 16
#define Ej 2048
#define Jn 40000
#define Jpad 40064
#define KP 112            // A packed K: e fp16 (single term)
#define RB 224            // bytes per packed A row in global
#define ST 240            // smem row stride (conflict-free: 15*16)
#define JT 128            // j rows per CTA
#define NJT (Jpad/JT)     // 313
#define SM_A (JT*ST)               // 30720
#define SM_B (128*ST)              // 30720 per buf (4 batches x 32 rows)
#define SM_TOTAL (SM_A + 2*SM_B)   // 92160  -> 2 CTAs/SM

// ---------------- device scratch (no runtime allocs) ----------------
__device__ float g_h   [Nn*Hh];
__device__ float g_m   [Nn*Hh];
__device__ float g_agg [Nn*Hh];
__device__ float g_h2  [Nn*Hh];
__device__ float g_vtT [Bb*Hh*Ll];   // [b][h][l]
__device__ float g_vT  [Bb*Hh*Ll];   // [b][h][l]
__device__ float g_sh  [Bb*Hh];
__device__ float g_wihT[Hh*300];
__device__ float g_whhT[Hh*300];
__device__ __align__(16) __half g_epk[(size_t)Jpad*KP];     // [j][h]
__device__ __align__(16) __half g_cpk[(size_t)Bb*32*KP];    // [b][32][h]

__device__ __forceinline__ float sigm(float x) { return 1.0f / (1.0f + __expf(-x)); }

__device__ __forceinline__ uint32_t smem_u32(const void* p) {
    uint32_t a;
    asm("{ .reg .u64 t; cvta.to.shared.u64 t, %1; cvt.u32.u64 %0, t; }" : "=r"(a) : "l"(p));
    return a;
}
__device__ __forceinline__ void cp16(uint32_t dst, const void* src) {
    asm volatile("cp.async.cg.shared.global [%0], [%1], 16;" :: "r"(dst), "l"(src) : "memory");
}
__device__ __forceinline__ void ldsm_x4(uint32_t* r, uint32_t addr) {
    asm volatile("ldmatrix.sync.aligned.m8n8.x4.shared.b16 {%0,%1,%2,%3}, [%4];"
                 : "=r"(r[0]), "=r"(r[1]), "=r"(r[2]), "=r"(r[3]) : "r"(addr));
}
__device__ __forceinline__ void ldsm_x2(uint32_t* r, uint32_t addr) {
    asm volatile("ldmatrix.sync.aligned.m8n8.x2.shared.b16 {%0,%1}, [%2];"
                 : "=r"(r[0]), "=r"(r[1]) : "r"(addr));
}
__device__ __forceinline__ void mma16816(float* d, const uint32_t* a, const uint32_t* b) {
    asm volatile(
        "mma.sync.aligned.m16n8k16.row.col.f32.f16.f16.f32 "
        "{%0,%1,%2,%3}, {%4,%5,%6,%7}, {%8,%9}, {%0,%1,%2,%3};"
        : "+f"(d[0]), "+f"(d[1]), "+f"(d[2]), "+f"(d[3])
        : "r"(a[0]), "r"(a[1]), "r"(a[2]), "r"(a[3]), "r"(b[0]), "r"(b[1]));
}

// ================= K_prep_e: embed -> fp16 rows (K=112, zero-padded) =========
__global__ void k_prep_e(const float* __restrict__ embed) {
    int idx = blockIdx.x * 256 + threadIdx.x;     // pairs
    if (idx >= Jpad * (KP/2)) return;
    int j  = idx / (KP/2);
    int kp = (idx - j * (KP/2)) * 2;
    __half o[2];
    #pragma unroll
    for (int i = 0; i < 2; i++) {
        int h = kp + i;
        float v = (j < Jn && h < Hh) ? embed[(size_t)j * Hh + h] : 0.0f;
        o[i] = __float2half(v);
    }
    *(uint32_t*)(g_epk + (size_t)j * KP + kp) = *(uint32_t*)o;
}

// ================= K_prep_c: coef rows (vt, v+sh) fp16 =================
__global__ void k_prep_c() {
    int idx = blockIdx.x * 256 + threadIdx.x;
    if (idx >= Bb * 32 * KP) return;
    int h = idx % KP;
    int r = (idx / KP) & 31;
    int b = idx / (KP * 32);
    float v = 0.0f;
    if (h < Hh) {
        if (r < 16) v = g_vtT[b * Hh * Ll + h * Ll + r];
        else        v = g_vT [b * Hh * Ll + h * Ll + (r - 16)] + g_sh[b * Hh + h];
    }
    g_cpk[idx] = __float2half(v);
}

// ================= K_wt: transpose GRU weights =================
__global__ void k_wt(const float* __restrict__ wih, const float* __restrict__ whh) {
    int i = blockIdx.x * 256 + threadIdx.x;
    if (i < 300 * Hh) {
        int r = i / Hh, c = i % Hh;
        g_wihT[c * 300 + r] = wih[i];
        g_whhT[c * 300 + r] = whh[i];
    }
}

// ================= K1: gather + m = h @ ggc_w =================
__global__ void k_gather(const int* __restrict__ x, const float* __restrict__ embed,
                         const float* __restrict__ ggc) {
    __shared__ float hs[Hh];
    int i = blockIdx.x, t = threadIdx.x;
    if (t < Hh) {
        float v = embed[(size_t)x[i] * Hh + t];
        hs[t] = v;
        g_h[i * Hh + t] = v;
        g_agg[i * Hh + t] = 0.0f;
    }
    __syncthreads();
    if (t < Hh) {
        float acc = 0.0f;
        #pragma unroll 4
        for (int c = 0; c < Hh; c++) acc = fmaf(hs[c], ggc[c * Hh + t], acc);
        g_m[i * Hh + t] = acc;
    }
}

// ================= K2: scatter-add =================
__global__ void k_scatter(const int* __restrict__ ei, const float* __restrict__ ew) {
    int e = blockIdx.x, t = threadIdx.x;
    if (t < Hh) {
        int s = ei[e], d = ei[Ej + e];
        atomicAdd(&g_agg[d * Hh + t], ew[e] * g_m[s * Hh + t]);
    }
}

// ================= K3: GRU =================
__global__ void k_gru2(const float* __restrict__ bih, const float* __restrict__ bhh) {
    __shared__ float a_s[4][Hh], h_s[4][Hh];
    __shared__ float gi_s[4][300], gh_s[4][300];
    int nb = blockIdx.x * 4;
    int t = threadIdx.x;             // block 416
    for (int i = t; i < 4 * Hh; i += 416) {
        int n = i / Hh, c = i % Hh;
        a_s[n][c] = g_agg[(nb + n) * Hh + c];
        h_s[n][c] = g_h  [(nb + n) * Hh + c];
    }
    __syncthreads();
    if (t < 300) {
        float ai0 = bih[t], ai1 = ai0, ai2 = ai0, ai3 = ai0;
        float ah0 = bhh[t], ah1 = ah0, ah2 = ah0, ah3 = ah0;
        #pragma unroll 4
        for (int c = 0; c < Hh; c++) {
            float wv = g_wihT[c * 300 + t];
            float uv = g_whhT[c * 300 + t];
            ai0 = fmaf(a_s[0][c], wv, ai0); ah0 = fmaf(h_s[0][c], uv, ah0);
            ai1 = fmaf(a_s[1][c], wv, ai1); ah1 = fmaf(h_s[1][c], uv, ah1);
            ai2 = fmaf(a_s[2][c], wv, ai2); ah2 = fmaf(h_s[2][c], uv, ah2);
            ai3 = fmaf(a_s[3][c], wv, ai3); ah3 = fmaf(h_s[3][c], uv, ah3);
        }
        gi_s[0][t] = ai0; gi_s[1][t] = ai1; gi_s[2][t] = ai2; gi_s[3][t] = ai3;
        gh_s[0][t] = ah0; gh_s[1][t] = ah1; gh_s[2][t] = ah2; gh_s[3][t] = ah3;
    }
    __syncthreads();
    if (t < 400) {
        int n = t / Hh, k = t % Hh;
        float r  = sigm(gi_s[n][k]         + gh_s[n][k]);
        float zg = sigm(gi_s[n][Hh + k]    + gh_s[n][Hh + k]);
        float ng = tanhf(gi_s[n][2*Hh + k] + r * gh_s[n][2*Hh + k]);
        g_h2[(nb + n) * Hh + k] = (1.0f - zg) * ng + zg * h_s[n][k];
    }
}

// ================= K4: attention readout =================
__global__ void k_attn(const float* __restrict__ W1w, const float* __restrict__ W1b,
                       const float* __restrict__ W2w, const float* __restrict__ W2b,
                       const float* __restrict__ Wtw, const float* __restrict__ Wtb,
                       const float* __restrict__ qw,  const float* __restrict__ qb,
                       const float* __restrict__ W3w, const float* __restrict__ W3b) {
    __shared__ float vs[Ll * Hh];
    __shared__ float t1[Hh];
    __shared__ float a_s[Ll * Hh];
    __shared__ float alpha_s[Ll];
    __shared__ float sg[Hh];
    int b = blockIdx.x, t = threadIdx.x;

    for (int i = t; i < Ll * Hh; i += 128) vs[i] = g_h2[b * Ll * Hh + i];
    __syncthreads();

    if (t < Hh) {
        float acc = W1b[t];
        const float* w = W1w + t * Hh;
        #pragma unroll 4
        for (int c = 0; c < Hh; c++) acc = fmaf(vs[15 * Hh + c], w[c], acc);
        t1[t] = acc;
    }
    __syncthreads();

    for (int idx = t; idx < Ll * Hh; idx += 128) {
        int l = idx / Hh, k = idx % Hh;
        float acc = W2b[k];
        const float* w = W2w + k * Hh;
        const float* vrow = vs + l * Hh;
        #pragma unroll 4
        for (int c = 0; c < Hh; c++) acc = fmaf(vrow[c], w[c], acc);
        a_s[idx] = sigm(t1[k] + acc);
    }
    __syncthreads();

    if (t < Ll) {
        float acc = qb[0];
        #pragma unroll 4
        for (int k = 0; k < Hh; k++) acc = fmaf(a_s[t * Hh + k], qw[k], acc);
        alpha_s[t] = acc;
    }
    __syncthreads();

    if (t < Hh) {
        float acc = 0.0f;
        #pragma unroll
        for (int l = 0; l < Ll; l++) acc = fmaf(alpha_s[l], vs[l * Hh + t], acc);
        sg[t] = acc;
    }
    __syncthreads();

    if (t < Hh) {
        float acc = W3b[t];
        const float* w = W3w + t * 2 * Hh;
        #pragma unroll 4
        for (int c = 0; c < Hh; c++)
            acc = fmaf(vs[15 * Hh + c], w[c], fmaf(sg[c], w[Hh + c], acc));
        g_sh[b * Hh + t] = acc;
    }

    for (int idx = t; idx < Ll * Hh; idx += 128) {
        int l = idx / Hh, k = idx % Hh;
        float acc = Wtb[k];
        const float* w = Wtw + k * Hh;
        const float* vrow = vs + l * Hh;
        #pragma unroll 4
        for (int c = 0; c < Hh; c++) acc = fmaf(vrow[c], w[c], acc);
        g_vtT[b * Hh * Ll + k * Ll + l] = acc;
        g_vT [b * Hh * Ll + k * Ll + l] = vs[l * Hh + k];
    }
}

// ================= K5: HMMA fused GEMM + softmax epilogue =================
// Single-term fp16: D = e.c, K=112. One MMA per acc per k-step (dep distance 16).
__global__ void __launch_bounds__(256, 2) k_ztc(float* __restrict__ z) {
    extern __shared__ __align__(128) char sm[];
    const uint32_t smA = smem_u32(sm);
    const uint32_t smB = smA + SM_A;
    int tid = threadIdx.x, warp = tid >> 5, lane = tid & 31;
    int wr = warp >> 1, wc = warp & 1;
    int jt = blockIdx.x, bs = blockIdx.y;      // bs: 0..3, 16 batches each

    // load A tile (128 rows x 224B)
    {
        const char* src = (const char*)g_epk + (size_t)jt * JT * RB;
        for (int i = tid; i < JT * 14; i += 256) {
            int r = i / 14, c = i - r * 14;
            cp16(smA + (uint32_t)r * ST + c * 16, src + (size_t)r * RB + c * 16);
        }
    }
    // load B for bt=0 (4 batches x 32 rows x 224B)
    {
        const char* src = (const char*)g_cpk + (size_t)(bs * 16) * 32 * RB;
        for (int i = tid; i < 128 * 14; i += 256) {
            int r = i / 14, c = i - r * 14;
            cp16(smB + (uint32_t)r * ST + c * 16, src + (size_t)r * RB + c * 16);
        }
    }
    asm volatile("cp.async.commit_group;" ::: "memory");
    asm volatile("cp.async.wait_group 0;" ::: "memory");
    __syncthreads();

    const uint32_t aBase = smA + (uint32_t)(wr * 32 + (lane & 15)) * ST + ((lane >> 4) << 4);
    const uint32_t bOff  = (uint32_t)(wc * 64 + (lane & 7)) * ST + (((lane >> 3) & 1) << 4);

    #pragma unroll 1
    for (int bt = 0; bt < 4; bt++) {
        if (bt + 1 < 4) {
            const char* src = (const char*)g_cpk + (size_t)(bs * 16 + (bt + 1) * 4) * 32 * RB;
            uint32_t dst = smB + (uint32_t)((bt + 1) & 1) * SM_B;
            for (int i = tid; i < 128 * 14; i += 256) {
                int r = i / 14, c = i - r * 14;
                cp16(dst + (uint32_t)r * ST + c * 16, src + (size_t)r * RB + c * 16);
            }
            asm volatile("cp.async.commit_group;" ::: "memory");
        }
        const uint32_t bBase = smB + (uint32_t)(bt & 1) * SM_B + bOff;

        float acc[2][8][4];
        #pragma unroll
        for (int mt = 0; mt < 2; mt++)
            #pragma unroll
            for (int nt = 0; nt < 8; nt++)
                #pragma unroll
                for (int q = 0; q < 4; q++) acc[mt][nt][q] = 0.0f;

        #pragma unroll
        for (int ksi = 0; ksi < 7; ksi++) {
            uint32_t ah[2][4];
            #pragma unroll
            for (int mt = 0; mt < 2; mt++)
                ldsm_x4(ah[mt], aBase + (uint32_t)mt * (16 * ST) + ksi * 32);
            #pragma unroll
            for (int nt = 0; nt < 8; nt++) {
                uint32_t bh[2];
                ldsm_x2(bh, bBase + (uint32_t)nt * (8 * ST) + ksi * 32);
                #pragma unroll
                for (int mt = 0; mt < 2; mt++)
                    mma16816(acc[mt][nt], ah[mt], bh);
            }
        }

        // epilogue: per (mt, bpair): p = nt {0,1}, c = nt {2,3} within the 4-nt group
        #pragma unroll
        for (int mt = 0; mt < 2; mt++) {
            #pragma unroll
            for (int bp = 0; bp < 2; bp++) {
                int nb = bp * 4;
                int b = bs * 16 + bt * 4 + wc * 2 + bp;
                int jA = jt * JT + wr * 32 + mt * 16 + (lane >> 2);
                #pragma unroll
                for (int half = 0; half < 2; half++) {   // 0: row jA, 1: row jA+8
                    int q0 = half * 2, q1 = half * 2 + 1;
                    float p0 = acc[mt][nb + 0][q0], p1 = acc[mt][nb + 0][q1];
                    float p2 = acc[mt][nb + 1][q0], p3 = acc[mt][nb + 1][q1];
                    float c0 = acc[mt][nb + 2][q0], c1 = acc[mt][nb + 2][q1];
                    float c2 = acc[mt][nb + 3][q0], c3 = acc[mt][nb + 3][q1];
                    float m = fmaxf(fmaxf(p0, p1), fmaxf(p2, p3));
                    m = fmaxf(m, __shfl_xor_sync(0xffffffffu, m, 1));
                    m = fmaxf(m, __shfl_xor_sync(0xffffffffu, m, 2));
                    float e0 = __expf(p0 - m), e1 = __expf(p1 - m);
                    float e2 = __expf(p2 - m), e3 = __expf(p3 - m);
                    float se = e0 + e1 + e2 + e3;
                    float ac = fmaf(e0, c0, fmaf(e1, c1, fmaf(e2, c2, e3 * c3)));
                    se += __shfl_xor_sync(0xffffffffu, se, 1);
                    ac += __shfl_xor_sync(0xffffffffu, ac, 1);
                    se += __shfl_xor_sync(0xffffffffu, se, 2);
                    ac += __shfl_xor_sync(0xffffffffu, ac, 2);
                    int j = jA + half * 8;
                    if ((lane & 3) == 0 && j < Jn)
                        z[(size_t)b * Jn + j] = ac / se;
                }
            }
        }

        if (bt + 1 < 4) asm volatile("cp.async.wait_group 0;" ::: "memory");
        __syncthreads();
    }
}

// ================= launch =================
extern "C" void kernel_launch(void* const* d_in, const int* in_sizes, int n_in,
                              void* d_out, int out_size) {
    const int*   x     = (const int*)  d_in[0];
    const int*   ei    = (const int*)  d_in[1];
    const float* ew    = (const float*)d_in[2];
    const float* embed = (const float*)d_in[4];
    const float* ggc   = (const float*)d_in[5];
    const float* wih   = (const float*)d_in[6];
    const float* whh   = (const float*)d_in[7];
    const float* bih   = (const float*)d_in[8];
    const float* bhh   = (const float*)d_in[9];
    const float* W1w   = (const float*)d_in[10];
    const float* W1b   = (const float*)d_in[11];
    const float* W2w   = (const float*)d_in[12];
    const float* W2b   = (const float*)d_in[13];
    const float* Wtw   = (const float*)d_in[14];
    const float* Wtb   = (const float*)d_in[15];
    const float* qw    = (const float*)d_in[16];
    const float* qb    = (const float*)d_in[17];
    const float* W3w   = (const float*)d_in[18];
    const float* W3b   = (const float*)d_in[19];
    float* z = (float*)d_out;

    cudaFuncSetAttribute(k_ztc, cudaFuncAttributeMaxDynamicSharedMemorySize, SM_TOTAL);

    int ne = Jpad * (KP / 2);
    k_prep_e<<<(ne + 255) / 256, 256>>>(embed);
    k_wt<<<(300 * Hh + 255) / 256, 256>>>(wih, whh);
    k_gather<<<Nn, 128>>>(x, embed, ggc);
    k_scatter<<<Ej, 128>>>(ei, ew);
    k_gru2<<<Nn / 4, 416>>>(bih, bhh);
    k_attn<<<Bb, 128>>>(W1w, W1b, W2w, W2b, Wtw, Wtb, qw, qb, W3w, W3b);
    int nc = Bb * 32 * KP;
    k_prep_c<<<(nc + 255) / 256, 256>>>();
    k_ztc<<<dim3(NJT, 4), 256, SM_TOTAL>>>(z);
}

// round 10
// speedup vs baseline: 2.2326x; 1.0135x over previous
#include <cuda_runtime.h>
#include <cuda_fp16.h>
#include <math.h>
#include <stdint.h>

#define Hh 100
#define Nn 1024
#define Bb 64
#define Ll 16
#define Ej 2048
#define Jn 40000
#define Jpad 40064
#define KP 112            // A packed K: e fp16 (single term)
#define RB 224            // bytes per packed A row in global
#define ST 240            // smem row stride (conflict-free: 15*16)
#define JT 128            // j rows per CTA
#define NJT (Jpad/JT)     // 313
#define SM_A (JT*ST)               // 30720
#define SM_B (128*ST)              // 30720 per buf (4 batches x 32 rows)
#define SM_TOTAL (SM_A + 2*SM_B)   // 92160  -> 2 CTAs/SM

// ---------------- device scratch (no runtime allocs) ----------------
__device__ float g_h   [Nn*Hh];
__device__ float g_m   [Nn*Hh];
__device__ float g_agg [Nn*Hh];
__device__ float g_h2  [Nn*Hh];
__device__ float g_vtT [Bb*Hh*Ll];   // [b][h][l]
__device__ float g_vT  [Bb*Hh*Ll];   // [b][h][l]
__device__ float g_sh  [Bb*Hh];
__device__ float g_wihT[Hh*300];
__device__ float g_whhT[Hh*300];
__device__ __align__(16) __half g_epk[(size_t)Jpad*KP];     // [j][h]
__device__ __align__(16) __half g_cpk[(size_t)Bb*32*KP];    // [b][32][h]

__device__ __forceinline__ float sigm(float x) { return 1.0f / (1.0f + __expf(-x)); }

__device__ __forceinline__ uint32_t smem_u32(const void* p) {
    uint32_t a;
    asm("{ .reg .u64 t; cvta.to.shared.u64 t, %1; cvt.u32.u64 %0, t; }" : "=r"(a) : "l"(p));
    return a;
}
__device__ __forceinline__ void cp16(uint32_t dst, const void* src) {
    asm volatile("cp.async.cg.shared.global [%0], [%1], 16;" :: "r"(dst), "l"(src) : "memory");
}
__device__ __forceinline__ void ldsm_x4(uint32_t* r, uint32_t addr) {
    asm volatile("ldmatrix.sync.aligned.m8n8.x4.shared.b16 {%0,%1,%2,%3}, [%4];"
                 : "=r"(r[0]), "=r"(r[1]), "=r"(r[2]), "=r"(r[3]) : "r"(addr));
}
__device__ __forceinline__ void mma16816(float* d, const uint32_t* a, const uint32_t* b) {
    asm volatile(
        "mma.sync.aligned.m16n8k16.row.col.f32.f16.f16.f32 "
        "{%0,%1,%2,%3}, {%4,%5,%6,%7}, {%8,%9}, {%0,%1,%2,%3};"
        : "+f"(d[0]), "+f"(d[1]), "+f"(d[2]), "+f"(d[3])
        : "r"(a[0]), "r"(a[1]), "r"(a[2]), "r"(a[3]), "r"(b[0]), "r"(b[1]));
}

// ================= K_prep_e: embed -> fp16 rows (K=112, zero-padded) =========
__global__ void k_prep_e(const float* __restrict__ embed) {
    int idx = blockIdx.x * 256 + threadIdx.x;     // pairs
    if (idx >= Jpad * (KP/2)) return;
    int j  = idx / (KP/2);
    int kp = (idx - j * (KP/2)) * 2;
    __half o[2];
    #pragma unroll
    for (int i = 0; i < 2; i++) {
        int h = kp + i;
        float v = (j < Jn && h < Hh) ? embed[(size_t)j * Hh + h] : 0.0f;
        o[i] = __float2half(v);
    }
    *(uint32_t*)(g_epk + (size_t)j * KP + kp) = *(uint32_t*)o;
}

// ================= K_prep_c: coef rows (vt, v+sh) fp16 =================
__global__ void k_prep_c() {
    int idx = blockIdx.x * 256 + threadIdx.x;
    if (idx >= Bb * 32 * KP) return;
    int h = idx % KP;
    int r = (idx / KP) & 31;
    int b = idx / (KP * 32);
    float v = 0.0f;
    if (h < Hh) {
        if (r < 16) v = g_vtT[b * Hh * Ll + h * Ll + r];
        else        v = g_vT [b * Hh * Ll + h * Ll + (r - 16)] + g_sh[b * Hh + h];
    }
    g_cpk[idx] = __float2half(v);
}

// ================= K_wt: transpose GRU weights =================
__global__ void k_wt(const float* __restrict__ wih, const float* __restrict__ whh) {
    int i = blockIdx.x * 256 + threadIdx.x;
    if (i < 300 * Hh) {
        int r = i / Hh, c = i % Hh;
        g_wihT[c * 300 + r] = wih[i];
        g_whhT[c * 300 + r] = whh[i];
    }
}

// ================= K1: gather + m = h @ ggc_w =================
__global__ void k_gather(const int* __restrict__ x, const float* __restrict__ embed,
                         const float* __restrict__ ggc) {
    __shared__ float hs[Hh];
    int i = blockIdx.x, t = threadIdx.x;
    if (t < Hh) {
        float v = embed[(size_t)x[i] * Hh + t];
        hs[t] = v;
        g_h[i * Hh + t] = v;
        g_agg[i * Hh + t] = 0.0f;
    }
    __syncthreads();
    if (t < Hh) {
        float acc = 0.0f;
        #pragma unroll 4
        for (int c = 0; c < Hh; c++) acc = fmaf(hs[c], ggc[c * Hh + t], acc);
        g_m[i * Hh + t] = acc;
    }
}

// ================= K2: scatter-add =================
__global__ void k_scatter(const int* __restrict__ ei, const float* __restrict__ ew) {
    int e = blockIdx.x, t = threadIdx.x;
    if (t < Hh) {
        int s = ei[e], d = ei[Ej + e];
        atomicAdd(&g_agg[d * Hh + t], ew[e] * g_m[s * Hh + t]);
    }
}

// ================= K3: GRU =================
__global__ void k_gru2(const float* __restrict__ bih, const float* __restrict__ bhh) {
    __shared__ float a_s[4][Hh], h_s[4][Hh];
    __shared__ float gi_s[4][300], gh_s[4][300];
    int nb = blockIdx.x * 4;
    int t = threadIdx.x;             // block 416
    for (int i = t; i < 4 * Hh; i += 416) {
        int n = i / Hh, c = i % Hh;
        a_s[n][c] = g_agg[(nb + n) * Hh + c];
        h_s[n][c] = g_h  [(nb + n) * Hh + c];
    }
    __syncthreads();
    if (t < 300) {
        float ai0 = bih[t], ai1 = ai0, ai2 = ai0, ai3 = ai0;
        float ah0 = bhh[t], ah1 = ah0, ah2 = ah0, ah3 = ah0;
        #pragma unroll 4
        for (int c = 0; c < Hh; c++) {
            float wv = g_wihT[c * 300 + t];
            float uv = g_whhT[c * 300 + t];
            ai0 = fmaf(a_s[0][c], wv, ai0); ah0 = fmaf(h_s[0][c], uv, ah0);
            ai1 = fmaf(a_s[1][c], wv, ai1); ah1 = fmaf(h_s[1][c], uv, ah1);
            ai2 = fmaf(a_s[2][c], wv, ai2); ah2 = fmaf(h_s[2][c], uv, ah2);
            ai3 = fmaf(a_s[3][c], wv, ai3); ah3 = fmaf(h_s[3][c], uv, ah3);
        }
        gi_s[0][t] = ai0; gi_s[1][t] = ai1; gi_s[2][t] = ai2; gi_s[3][t] = ai3;
        gh_s[0][t] = ah0; gh_s[1][t] = ah1; gh_s[2][t] = ah2; gh_s[3][t] = ah3;
    }
    __syncthreads();
    if (t < 400) {
        int n = t / Hh, k = t % Hh;
        float r  = sigm(gi_s[n][k]         + gh_s[n][k]);
        float zg = sigm(gi_s[n][Hh + k]    + gh_s[n][Hh + k]);
        float ng = tanhf(gi_s[n][2*Hh + k] + r * gh_s[n][2*Hh + k]);
        g_h2[(nb + n) * Hh + k] = (1.0f - zg) * ng + zg * h_s[n][k];
    }
}

// ================= K4: attention readout =================
__global__ void k_attn(const float* __restrict__ W1w, const float* __restrict__ W1b,
                       const float* __restrict__ W2w, const float* __restrict__ W2b,
                       const float* __restrict__ Wtw, const float* __restrict__ Wtb,
                       const float* __restrict__ qw,  const float* __restrict__ qb,
                       const float* __restrict__ W3w, const float* __restrict__ W3b) {
    __shared__ float vs[Ll * Hh];
    __shared__ float t1[Hh];
    __shared__ float a_s[Ll * Hh];
    __shared__ float alpha_s[Ll];
    __shared__ float sg[Hh];
    int b = blockIdx.x, t = threadIdx.x;

    for (int i = t; i < Ll * Hh; i += 128) vs[i] = g_h2[b * Ll * Hh + i];
    __syncthreads();

    if (t < Hh) {
        float acc = W1b[t];
        const float* w = W1w + t * Hh;
        #pragma unroll 4
        for (int c = 0; c < Hh; c++) acc = fmaf(vs[15 * Hh + c], w[c], acc);
        t1[t] = acc;
    }
    __syncthreads();

    for (int idx = t; idx < Ll * Hh; idx += 128) {
        int l = idx / Hh, k = idx % Hh;
        float acc = W2b[k];
        const float* w = W2w + k * Hh;
        const float* vrow = vs + l * Hh;
        #pragma unroll 4
        for (int c = 0; c < Hh; c++) acc = fmaf(vrow[c], w[c], acc);
        a_s[idx] = sigm(t1[k] + acc);
    }
    __syncthreads();

    if (t < Ll) {
        float acc = qb[0];
        #pragma unroll 4
        for (int k = 0; k < Hh; k++) acc = fmaf(a_s[t * Hh + k], qw[k], acc);
        alpha_s[t] = acc;
    }
    __syncthreads();

    if (t < Hh) {
        float acc = 0.0f;
        #pragma unroll
        for (int l = 0; l < Ll; l++) acc = fmaf(alpha_s[l], vs[l * Hh + t], acc);
        sg[t] = acc;
    }
    __syncthreads();

    if (t < Hh) {
        float acc = W3b[t];
        const float* w = W3w + t * 2 * Hh;
        #pragma unroll 4
        for (int c = 0; c < Hh; c++)
            acc = fmaf(vs[15 * Hh + c], w[c], fmaf(sg[c], w[Hh + c], acc));
        g_sh[b * Hh + t] = acc;
    }

    for (int idx = t; idx < Ll * Hh; idx += 128) {
        int l = idx / Hh, k = idx % Hh;
        float acc = Wtb[k];
        const float* w = Wtw + k * Hh;
        const float* vrow = vs + l * Hh;
        #pragma unroll 4
        for (int c = 0; c < Hh; c++) acc = fmaf(vrow[c], w[c], acc);
        g_vtT[b * Hh * Ll + k * Ll + l] = acc;
        g_vT [b * Hh * Ll + k * Ll + l] = vs[l * Hh + k];
    }
}

// ================= K5: HMMA fused GEMM + softmax epilogue =================
// fp16 single-term, K=112. B via ldmatrix.x4 (n16xk16), fragments double-buffered
// so LDSM latency overlaps MMA issue. 6 LDSM : 16 MMA per k-step.
__global__ void __launch_bounds__(256, 2) k_ztc(float* __restrict__ z) {
    extern __shared__ __align__(128) char sm[];
    const uint32_t smA = smem_u32(sm);
    const uint32_t smB = smA + SM_A;
    int tid = threadIdx.x, warp = tid >> 5, lane = tid & 31;
    int wr = warp >> 1, wc = warp & 1;
    int jt = blockIdx.x, bs = blockIdx.y;      // bs: 0..3, 16 batches each

    // load A tile (128 rows x 224B)
    {
        const char* src = (const char*)g_epk + (size_t)jt * JT * RB;
        for (int i = tid; i < JT * 14; i += 256) {
            int r = i / 14, c = i - r * 14;
            cp16(smA + (uint32_t)r * ST + c * 16, src + (size_t)r * RB + c * 16);
        }
    }
    // load B for bt=0 (4 batches x 32 rows x 224B)
    {
        const char* src = (const char*)g_cpk + (size_t)(bs * 16) * 32 * RB;
        for (int i = tid; i < 128 * 14; i += 256) {
            int r = i / 14, c = i - r * 14;
            cp16(smB + (uint32_t)r * ST + c * 16, src + (size_t)r * RB + c * 16);
        }
    }
    asm volatile("cp.async.commit_group;" ::: "memory");
    asm volatile("cp.async.wait_group 0;" ::: "memory");
    __syncthreads();

    // A x4: lanes 0-15 -> 16 rows, lanes 16-31 -> +16B col offset
    const uint32_t aBase = smA + (uint32_t)(wr * 32 + (lane & 15)) * ST + ((lane >> 4) << 4);
    // B x4 (n16 x k16): row = wc*64 + (lane&7) + ((lane>=16)?8:0), koff = ((lane>>3)&1)*16
    const uint32_t bOff4 = (uint32_t)(wc * 64 + (lane & 7) + ((lane >> 4) << 3)) * ST
                         + (((lane >> 3) & 1) << 4);

    #pragma unroll 1
    for (int bt = 0; bt < 4; bt++) {
        if (bt + 1 < 4) {
            const char* src = (const char*)g_cpk + (size_t)(bs * 16 + (bt + 1) * 4) * 32 * RB;
            uint32_t dst = smB + (uint32_t)((bt + 1) & 1) * SM_B;
            for (int i = tid; i < 128 * 14; i += 256) {
                int r = i / 14, c = i - r * 14;
                cp16(dst + (uint32_t)r * ST + c * 16, src + (size_t)r * RB + c * 16);
            }
            asm volatile("cp.async.commit_group;" ::: "memory");
        }
        const uint32_t bBase = smB + (uint32_t)(bt & 1) * SM_B + bOff4;

        float acc[2][8][4];
        #pragma unroll
        for (int mt = 0; mt < 2; mt++)
            #pragma unroll
            for (int nt = 0; nt < 8; nt++)
                #pragma unroll
                for (int q = 0; q < 4; q++) acc[mt][nt][q] = 0.0f;

        uint32_t af[2][2][4], bf[2][4][4];
        // preload k-step 0
        #pragma unroll
        for (int mt = 0; mt < 2; mt++)
            ldsm_x4(af[0][mt], aBase + (uint32_t)mt * (16 * ST));
        #pragma unroll
        for (int np = 0; np < 4; np++)
            ldsm_x4(bf[0][np], bBase + (uint32_t)np * (16 * ST));

        #pragma unroll
        for (int ksi = 0; ksi < 7; ksi++) {
            int cur = ksi & 1, nxt = cur ^ 1;
            if (ksi < 6) {
                #pragma unroll
                for (int mt = 0; mt < 2; mt++)
                    ldsm_x4(af[nxt][mt], aBase + (uint32_t)mt * (16 * ST) + (ksi + 1) * 32);
                #pragma unroll
                for (int np = 0; np < 4; np++)
                    ldsm_x4(bf[nxt][np], bBase + (uint32_t)np * (16 * ST) + (ksi + 1) * 32);
            }
            #pragma unroll
            for (int np = 0; np < 4; np++) {
                #pragma unroll
                for (int mt = 0; mt < 2; mt++) {
                    mma16816(acc[mt][2 * np],     af[cur][mt], bf[cur][np]);
                    mma16816(acc[mt][2 * np + 1], af[cur][mt], bf[cur][np] + 2);
                }
            }
        }

        // epilogue: per (mt, bpair): p = nt {0,1}, c = nt {2,3} within the 4-nt group
        #pragma unroll
        for (int mt = 0; mt < 2; mt++) {
            #pragma unroll
            for (int bp = 0; bp < 2; bp++) {
                int nb = bp * 4;
                int b = bs * 16 + bt * 4 + wc * 2 + bp;
                int jA = jt * JT + wr * 32 + mt * 16 + (lane >> 2);
                #pragma unroll
                for (int half = 0; half < 2; half++) {   // 0: row jA, 1: row jA+8
                    int q0 = half * 2, q1 = half * 2 + 1;
                    float p0 = acc[mt][nb + 0][q0], p1 = acc[mt][nb + 0][q1];
                    float p2 = acc[mt][nb + 1][q0], p3 = acc[mt][nb + 1][q1];
                    float c0 = acc[mt][nb + 2][q0], c1 = acc[mt][nb + 2][q1];
                    float c2 = acc[mt][nb + 3][q0], c3 = acc[mt][nb + 3][q1];
                    float m = fmaxf(fmaxf(p0, p1), fmaxf(p2, p3));
                    m = fmaxf(m, __shfl_xor_sync(0xffffffffu, m, 1));
                    m = fmaxf(m, __shfl_xor_sync(0xffffffffu, m, 2));
                    float e0 = __expf(p0 - m), e1 = __expf(p1 - m);
                    float e2 = __expf(p2 - m), e3 = __expf(p3 - m);
                    float se = e0 + e1 + e2 + e3;
                    float ac = fmaf(e0, c0, fmaf(e1, c1, fmaf(e2, c2, e3 * c3)));
                    se += __shfl_xor_sync(0xffffffffu, se, 1);
                    ac += __shfl_xor_sync(0xffffffffu, ac, 1);
                    se += __shfl_xor_sync(0xffffffffu, se, 2);
                    ac += __shfl_xor_sync(0xffffffffu, ac, 2);
                    int j = jA + half * 8;
                    if ((lane & 3) == 0 && j < Jn)
                        z[(size_t)b * Jn + j] = ac / se;
                }
            }
        }

        if (bt + 1 < 4) asm volatile("cp.async.wait_group 0;" ::: "memory");
        __syncthreads();
    }
}

// ================= launch =================
extern "C" void kernel_launch(void* const* d_in, const int* in_sizes, int n_in,
                              void* d_out, int out_size) {
    const int*   x     = (const int*)  d_in[0];
    const int*   ei    = (const int*)  d_in[1];
    const float* ew    = (const float*)d_in[2];
    const float* embed = (const float*)d_in[4];
    const float* ggc   = (const float*)d_in[5];
    const float* wih   = (const float*)d_in[6];
    const float* whh   = (const float*)d_in[7];
    const float* bih   = (const float*)d_in[8];
    const float* bhh   = (const float*)d_in[9];
    const float* W1w   = (const float*)d_in[10];
    const float* W1b   = (const float*)d_in[11];
    const float* W2w   = (const float*)d_in[12];
    const float* W2b   = (const float*)d_in[13];
    const float* Wtw   = (const float*)d_in[14];
    const float* Wtb   = (const float*)d_in[15];
    const float* qw    = (const float*)d_in[16];
    const float* qb    = (const float*)d_in[17];
    const float* W3w   = (const float*)d_in[18];
    const float* W3b   = (const float*)d_in[19];
    float* z = (float*)d_out;

    cudaFuncSetAttribute(k_ztc, cudaFuncAttributeMaxDynamicSharedMemorySize, SM_TOTAL);

    int ne = Jpad * (KP / 2);
    k_prep_e<<<(ne + 255) / 256, 256>>>(embed);
    k_wt<<<(300 * Hh + 255) / 256, 256>>>(wih, whh);
    k_gather<<<Nn, 128>>>(x, embed, ggc);
    k_scatter<<<Ej, 128>>>(ei, ew);
    k_gru2<<<Nn / 4, 416>>>(bih, bhh);
    k_attn<<<Bb, 128>>>(W1w, W1b, W2w, W2b, Wtw, Wtb, qw, qb, W3w, W3b);
    int nc = Bb * 32 * KP;
    k_prep_c<<<(nc + 255) / 256, 256>>>();
    k_ztc<<<dim3(NJT, 4), 256, SM_TOTAL>>>(z);
}

// round 11
// speedup vs baseline: 2.2357x; 1.0014x over previous
#include <cuda_runtime.h>
#include <cuda_fp16.h>
#include <math.h>
#include <stdint.h>

#define Hh 100
#define Nn 1024
#define Bb 64
#define Ll 16
#define Ej 2048
#define Jn 40000
#define Jpad 40064
#define KP 112            // A packed K: e fp16 (single term)
#define RB 224            // bytes per packed A row in global
#define ST 240            // smem row stride (conflict-free: 15*16)
#define JT 128            // j rows per CTA
#define NJT (Jpad/JT)     // 313
#define SM_A (JT*ST)               // 30720
#define SM_B (64*ST)               // 15360 per buf (2 batches x 32 rows)
#define SM_TOTAL (SM_A + 2*SM_B)   // 61440  -> 3 CTAs/SM

// ---------------- device scratch (no runtime allocs) ----------------
__device__ float g_h   [Nn*Hh];
__device__ float g_m   [Nn*Hh];
__device__ float g_agg [Nn*Hh];
__device__ float g_h2  [Nn*Hh];
__device__ float g_vtT [Bb*Hh*Ll];   // [b][h][l]
__device__ float g_vT  [Bb*Hh*Ll];   // [b][h][l]
__device__ float g_sh  [Bb*Hh];
__device__ float g_wihT[Hh*300];
__device__ float g_whhT[Hh*300];
__device__ __align__(16) __half g_epk[(size_t)Jpad*KP];     // [j][h]
__device__ __align__(16) __half g_cpk[(size_t)Bb*32*KP];    // [b][32][h]

__device__ __forceinline__ float sigm(float x) { return 1.0f / (1.0f + __expf(-x)); }

__device__ __forceinline__ uint32_t smem_u32(const void* p) {
    uint32_t a;
    asm("{ .reg .u64 t; cvta.to.shared.u64 t, %1; cvt.u32.u64 %0, t; }" : "=r"(a) : "l"(p));
    return a;
}
__device__ __forceinline__ void cp16(uint32_t dst, const void* src) {
    asm volatile("cp.async.cg.shared.global [%0], [%1], 16;" :: "r"(dst), "l"(src) : "memory");
}
__device__ __forceinline__ void ldsm_x4(uint32_t* r, uint32_t addr) {
    asm volatile("ldmatrix.sync.aligned.m8n8.x4.shared.b16 {%0,%1,%2,%3}, [%4];"
                 : "=r"(r[0]), "=r"(r[1]), "=r"(r[2]), "=r"(r[3]) : "r"(addr));
}
__device__ __forceinline__ void mma16816(float* d, const uint32_t* a, const uint32_t* b) {
    asm volatile(
        "mma.sync.aligned.m16n8k16.row.col.f32.f16.f16.f32 "
        "{%0,%1,%2,%3}, {%4,%5,%6,%7}, {%8,%9}, {%0,%1,%2,%3};"
        : "+f"(d[0]), "+f"(d[1]), "+f"(d[2]), "+f"(d[3])
        : "r"(a[0]), "r"(a[1]), "r"(a[2]), "r"(a[3]), "r"(b[0]), "r"(b[1]));
}

// ================= K_prep_e: embed -> fp16 rows (K=112, zero-padded) =========
__global__ void k_prep_e(const float* __restrict__ embed) {
    int idx = blockIdx.x * 256 + threadIdx.x;     // pairs
    if (idx >= Jpad * (KP/2)) return;
    int j  = idx / (KP/2);
    int kp = (idx - j * (KP/2)) * 2;
    __half o[2];
    #pragma unroll
    for (int i = 0; i < 2; i++) {
        int h = kp + i;
        float v = (j < Jn && h < Hh) ? embed[(size_t)j * Hh + h] : 0.0f;
        o[i] = __float2half(v);
    }
    *(uint32_t*)(g_epk + (size_t)j * KP + kp) = *(uint32_t*)o;
}

// ================= K_prep_c: coef rows (vt, v+sh) fp16 =================
__global__ void k_prep_c() {
    int idx = blockIdx.x * 256 + threadIdx.x;
    if (idx >= Bb * 32 * KP) return;
    int h = idx % KP;
    int r = (idx / KP) & 31;
    int b = idx / (KP * 32);
    float v = 0.0f;
    if (h < Hh) {
        if (r < 16) v = g_vtT[b * Hh * Ll + h * Ll + r];
        else        v = g_vT [b * Hh * Ll + h * Ll + (r - 16)] + g_sh[b * Hh + h];
    }
    g_cpk[idx] = __float2half(v);
}

// ================= K_wt: transpose GRU weights =================
__global__ void k_wt(const float* __restrict__ wih, const float* __restrict__ whh) {
    int i = blockIdx.x * 256 + threadIdx.x;
    if (i < 300 * Hh) {
        int r = i / Hh, c = i % Hh;
        g_wihT[c * 300 + r] = wih[i];
        g_whhT[c * 300 + r] = whh[i];
    }
}

// ================= K1: gather + m = h @ ggc_w =================
__global__ void k_gather(const int* __restrict__ x, const float* __restrict__ embed,
                         const float* __restrict__ ggc) {
    __shared__ float hs[Hh];
    int i = blockIdx.x, t = threadIdx.x;
    if (t < Hh) {
        float v = embed[(size_t)x[i] * Hh + t];
        hs[t] = v;
        g_h[i * Hh + t] = v;
        g_agg[i * Hh + t] = 0.0f;
    }
    __syncthreads();
    if (t < Hh) {
        float acc = 0.0f;
        #pragma unroll 4
        for (int c = 0; c < Hh; c++) acc = fmaf(hs[c], ggc[c * Hh + t], acc);
        g_m[i * Hh + t] = acc;
    }
}

// ================= K2: scatter-add =================
__global__ void k_scatter(const int* __restrict__ ei, const float* __restrict__ ew) {
    int e = blockIdx.x, t = threadIdx.x;
    if (t < Hh) {
        int s = ei[e], d = ei[Ej + e];
        atomicAdd(&g_agg[d * Hh + t], ew[e] * g_m[s * Hh + t]);
    }
}

// ================= K3: GRU =================
__global__ void k_gru2(const float* __restrict__ bih, const float* __restrict__ bhh) {
    __shared__ float a_s[4][Hh], h_s[4][Hh];
    __shared__ float gi_s[4][300], gh_s[4][300];
    int nb = blockIdx.x * 4;
    int t = threadIdx.x;             // block 416
    for (int i = t; i < 4 * Hh; i += 416) {
        int n = i / Hh, c = i % Hh;
        a_s[n][c] = g_agg[(nb + n) * Hh + c];
        h_s[n][c] = g_h  [(nb + n) * Hh + c];
    }
    __syncthreads();
    if (t < 300) {
        float ai0 = bih[t], ai1 = ai0, ai2 = ai0, ai3 = ai0;
        float ah0 = bhh[t], ah1 = ah0, ah2 = ah0, ah3 = ah0;
        #pragma unroll 4
        for (int c = 0; c < Hh; c++) {
            float wv = g_wihT[c * 300 + t];
            float uv = g_whhT[c * 300 + t];
            ai0 = fmaf(a_s[0][c], wv, ai0); ah0 = fmaf(h_s[0][c], uv, ah0);
            ai1 = fmaf(a_s[1][c], wv, ai1); ah1 = fmaf(h_s[1][c], uv, ah1);
            ai2 = fmaf(a_s[2][c], wv, ai2); ah2 = fmaf(h_s[2][c], uv, ah2);
            ai3 = fmaf(a_s[3][c], wv, ai3); ah3 = fmaf(h_s[3][c], uv, ah3);
        }
        gi_s[0][t] = ai0; gi_s[1][t] = ai1; gi_s[2][t] = ai2; gi_s[3][t] = ai3;
        gh_s[0][t] = ah0; gh_s[1][t] = ah1; gh_s[2][t] = ah2; gh_s[3][t] = ah3;
    }
    __syncthreads();
    if (t < 400) {
        int n = t / Hh, k = t % Hh;
        float r  = sigm(gi_s[n][k]         + gh_s[n][k]);
        float zg = sigm(gi_s[n][Hh + k]    + gh_s[n][Hh + k]);
        float ng = tanhf(gi_s[n][2*Hh + k] + r * gh_s[n][2*Hh + k]);
        g_h2[(nb + n) * Hh + k] = (1.0f - zg) * ng + zg * h_s[n][k];
    }
}

// ================= K4: attention readout =================
__global__ void k_attn(const float* __restrict__ W1w, const float* __restrict__ W1b,
                       const float* __restrict__ W2w, const float* __restrict__ W2b,
                       const float* __restrict__ Wtw, const float* __restrict__ Wtb,
                       const float* __restrict__ qw,  const float* __restrict__ qb,
                       const float* __restrict__ W3w, const float* __restrict__ W3b) {
    __shared__ float vs[Ll * Hh];
    __shared__ float t1[Hh];
    __shared__ float a_s[Ll * Hh];
    __shared__ float alpha_s[Ll];
    __shared__ float sg[Hh];
    int b = blockIdx.x, t = threadIdx.x;

    for (int i = t; i < Ll * Hh; i += 128) vs[i] = g_h2[b * Ll * Hh + i];
    __syncthreads();

    if (t < Hh) {
        float acc = W1b[t];
        const float* w = W1w + t * Hh;
        #pragma unroll 4
        for (int c = 0; c < Hh; c++) acc = fmaf(vs[15 * Hh + c], w[c], acc);
        t1[t] = acc;
    }
    __syncthreads();

    for (int idx = t; idx < Ll * Hh; idx += 128) {
        int l = idx / Hh, k = idx % Hh;
        float acc = W2b[k];
        const float* w = W2w + k * Hh;
        const float* vrow = vs + l * Hh;
        #pragma unroll 4
        for (int c = 0; c < Hh; c++) acc = fmaf(vrow[c], w[c], acc);
        a_s[idx] = sigm(t1[k] + acc);
    }
    __syncthreads();

    if (t < Ll) {
        float acc = qb[0];
        #pragma unroll 4
        for (int k = 0; k < Hh; k++) acc = fmaf(a_s[t * Hh + k], qw[k], acc);
        alpha_s[t] = acc;
    }
    __syncthreads();

    if (t < Hh) {
        float acc = 0.0f;
        #pragma unroll
        for (int l = 0; l < Ll; l++) acc = fmaf(alpha_s[l], vs[l * Hh + t], acc);
        sg[t] = acc;
    }
    __syncthreads();

    if (t < Hh) {
        float acc = W3b[t];
        const float* w = W3w + t * 2 * Hh;
        #pragma unroll 4
        for (int c = 0; c < Hh; c++)
            acc = fmaf(vs[15 * Hh + c], w[c], fmaf(sg[c], w[Hh + c], acc));
        g_sh[b * Hh + t] = acc;
    }

    for (int idx = t; idx < Ll * Hh; idx += 128) {
        int l = idx / Hh, k = idx % Hh;
        float acc = Wtb[k];
        const float* w = Wtw + k * Hh;
        const float* vrow = vs + l * Hh;
        #pragma unroll 4
        for (int c = 0; c < Hh; c++) acc = fmaf(vrow[c], w[c], acc);
        g_vtT[b * Hh * Ll + k * Ll + l] = acc;
        g_vT [b * Hh * Ll + k * Ll + l] = vs[l * Hh + k];
    }
}

// ================= K5: HMMA fused GEMM + softmax epilogue =================
// fp16 single-term, K=112. 3 CTAs/SM (smem 61.4KB, ~80 regs).
// Per bt: 2 batches (64 B-rows). Warp m32 x n32 (1 batch per wc).
__global__ void __launch_bounds__(256, 3) k_ztc(float* __restrict__ z) {
    extern __shared__ __align__(128) char sm[];
    const uint32_t smA = smem_u32(sm);
    const uint32_t smB = smA + SM_A;
    int tid = threadIdx.x, warp = tid >> 5, lane = tid & 31;
    int wr = warp >> 1, wc = warp & 1;
    int jt = blockIdx.x, bs = blockIdx.y;      // bs: 0..3, 16 batches each

    // load A tile (128 rows x 224B)
    {
        const char* src = (const char*)g_epk + (size_t)jt * JT * RB;
        for (int i = tid; i < JT * 14; i += 256) {
            int r = i / 14, c = i - r * 14;
            cp16(smA + (uint32_t)r * ST + c * 16, src + (size_t)r * RB + c * 16);
        }
    }
    // load B for bt=0 (2 batches x 32 rows x 224B)
    {
        const char* src = (const char*)g_cpk + (size_t)(bs * 16) * 32 * RB;
        for (int i = tid; i < 64 * 14; i += 256) {
            int r = i / 14, c = i - r * 14;
            cp16(smB + (uint32_t)r * ST + c * 16, src + (size_t)r * RB + c * 16);
        }
    }
    asm volatile("cp.async.commit_group;" ::: "memory");
    asm volatile("cp.async.wait_group 0;" ::: "memory");
    __syncthreads();

    // A x4: lanes 0-15 -> 16 rows, lanes 16-31 -> +16B col offset
    const uint32_t aBase = smA + (uint32_t)(wr * 32 + (lane & 15)) * ST + ((lane >> 4) << 4);
    // B x4 (n16 x k16): row = wc*32 + (lane&7) + ((lane>=16)?8:0), koff = ((lane>>3)&1)*16
    const uint32_t bOff4 = (uint32_t)(wc * 32 + (lane & 7) + ((lane >> 4) << 3)) * ST
                         + (((lane >> 3) & 1) << 4);

    #pragma unroll 1
    for (int bt = 0; bt < 8; bt++) {
        if (bt + 1 < 8) {
            const char* src = (const char*)g_cpk + (size_t)(bs * 16 + (bt + 1) * 2) * 32 * RB;
            uint32_t dst = smB + (uint32_t)((bt + 1) & 1) * SM_B;
            for (int i = tid; i < 64 * 14; i += 256) {
                int r = i / 14, c = i - r * 14;
                cp16(dst + (uint32_t)r * ST + c * 16, src + (size_t)r * RB + c * 16);
            }
            asm volatile("cp.async.commit_group;" ::: "memory");
        }
        const uint32_t bBase = smB + (uint32_t)(bt & 1) * SM_B + bOff4;

        float acc[2][4][4];
        #pragma unroll
        for (int mt = 0; mt < 2; mt++)
            #pragma unroll
            for (int nt = 0; nt < 4; nt++)
                #pragma unroll
                for (int q = 0; q < 4; q++) acc[mt][nt][q] = 0.0f;

        #pragma unroll
        for (int ksi = 0; ksi < 7; ksi++) {
            uint32_t af[2][4], bf[2][4];
            #pragma unroll
            for (int mt = 0; mt < 2; mt++)
                ldsm_x4(af[mt], aBase + (uint32_t)mt * (16 * ST) + ksi * 32);
            #pragma unroll
            for (int np = 0; np < 2; np++)
                ldsm_x4(bf[np], bBase + (uint32_t)np * (16 * ST) + ksi * 32);
            #pragma unroll
            for (int np = 0; np < 2; np++) {
                #pragma unroll
                for (int mt = 0; mt < 2; mt++) {
                    mma16816(acc[mt][2 * np],     af[mt], bf[np]);
                    mma16816(acc[mt][2 * np + 1], af[mt], bf[np] + 2);
                }
            }
        }

        // epilogue: p = acc[mt][0/1], c = acc[mt][2/3]; batch = bs*16 + bt*2 + wc
        int b = bs * 16 + bt * 2 + wc;
        #pragma unroll
        for (int mt = 0; mt < 2; mt++) {
            int jA = jt * JT + wr * 32 + mt * 16 + (lane >> 2);
            #pragma unroll
            for (int half = 0; half < 2; half++) {   // 0: row jA, 1: row jA+8
                int q0 = half * 2, q1 = half * 2 + 1;
                float p0 = acc[mt][0][q0], p1 = acc[mt][0][q1];
                float p2 = acc[mt][1][q0], p3 = acc[mt][1][q1];
                float c0 = acc[mt][2][q0], c1 = acc[mt][2][q1];
                float c2 = acc[mt][3][q0], c3 = acc[mt][3][q1];
                float m = fmaxf(fmaxf(p0, p1), fmaxf(p2, p3));
                m = fmaxf(m, __shfl_xor_sync(0xffffffffu, m, 1));
                m = fmaxf(m, __shfl_xor_sync(0xffffffffu, m, 2));
                float e0 = __expf(p0 - m), e1 = __expf(p1 - m);
                float e2 = __expf(p2 - m), e3 = __expf(p3 - m);
                float se = e0 + e1 + e2 + e3;
                float ac = fmaf(e0, c0, fmaf(e1, c1, fmaf(e2, c2, e3 * c3)));
                se += __shfl_xor_sync(0xffffffffu, se, 1);
                ac += __shfl_xor_sync(0xffffffffu, ac, 1);
                se += __shfl_xor_sync(0xffffffffu, se, 2);
                ac += __shfl_xor_sync(0xffffffffu, ac, 2);
                int j = jA + half * 8;
                if ((lane & 3) == 0 && j < Jn)
                    z[(size_t)b * Jn + j] = ac / se;
            }
        }

        if (bt + 1 < 8) asm volatile("cp.async.wait_group 0;" ::: "memory");
        __syncthreads();
    }
}

// ================= launch =================
extern "C" void kernel_launch(void* const* d_in, const int* in_sizes, int n_in,
                              void* d_out, int out_size) {
    const int*   x     = (const int*)  d_in[0];
    const int*   ei    = (const int*)  d_in[1];
    const float* ew    = (const float*)d_in[2];
    const float* embed = (const float*)d_in[4];
    const float* ggc   = (const float*)d_in[5];
    const float* wih   = (const float*)d_in[6];
    const float* whh   = (const float*)d_in[7];
    const float* bih   = (const float*)d_in[8];
    const float* bhh   = (const float*)d_in[9];
    const float* W1w   = (const float*)d_in[10];
    const float* W1b   = (const float*)d_in[11];
    const float* W2w   = (const float*)d_in[12];
    const float* W2b   = (const float*)d_in[13];
    const float* Wtw   = (const float*)d_in[14];
    const float* Wtb   = (const float*)d_in[15];
    const float* qw    = (const float*)d_in[16];
    const float* qb    = (const float*)d_in[17];
    const float* W3w   = (const float*)d_in[18];
    const float* W3b   = (const float*)d_in[19];
    float* z = (float*)d_out;

    cudaFuncSetAttribute(k_ztc, cudaFuncAttributeMaxDynamicSharedMemorySize, SM_TOTAL);

    int ne = Jpad * (KP / 2);
    k_prep_e<<<(ne + 255) / 256, 256>>>(embed);
    k_wt<<<(300 * Hh + 255) / 256, 256>>>(wih, whh);
    k_gather<<<Nn, 128>>>(x, embed, ggc);
    k_scatter<<<Ej, 128>>>(ei, ew);
    k_gru2<<<Nn / 4, 416>>>(bih, bhh);
    k_attn<<<Bb, 128>>>(W1w, W1b, W2w, W2b, Wtw, Wtb, qw, qb, W3w, W3b);
    int nc = Bb * 32 * KP;
    k_prep_c<<<(nc + 255) / 256, 256>>>();
    k_ztc<<<dim3(NJT, 4), 256, SM_TOTAL>>>(z);
}

// round 12
// speedup vs baseline: 2.8800x; 1.2882x over previous
#include <cuda_runtime.h>
#include <cuda_fp16.h>
#include <math.h>
#include <stdint.h>

#define Hh 100
#define Nn 1024
#define Bb 64
#define Ll 16
#define Ej 2048
#define Jn 40000
#define Jpad 40064
#define KP 112            // A packed K: e fp16 (single term)
#define RB 224            // bytes per packed row in global
#define ST 240            // smem row stride (conflict-free: 15*16)
#define JT 128            // j rows per CTA
#define NJT (Jpad/JT)     // 313
#define SM_A (JT*ST)               // 30720
#define SM_B (64*ST)               // 15360 per buf (2 batches x 32 rows)
#define SM_TOTAL (SM_A + 2*SM_B)   // 61440  -> 3 CTAs/SM

// K0 grid partition
#define PE_BLKS 8764       // prep_e: Jpad*56/256 exactly
#define WT_BLKS 118        // 30000 weights / 256
#define K0_GRID (PE_BLKS + WT_BLKS + Nn)

// ---------------- device scratch (no runtime allocs) ----------------
__device__ float g_h   [Nn*Hh];
__device__ float g_m   [Nn*Hh];
__device__ float g_agg [Nn*Hh];
__device__ float g_wihT[Hh*300];
__device__ float g_whhT[Hh*300];
__device__ __align__(16) __half g_epk[(size_t)Jpad*KP];     // [j][h]
__device__ __align__(16) __half g_cpk[(size_t)Bb*32*KP];    // [b][32][h]

__device__ __forceinline__ float sigm(float x) { return 1.0f / (1.0f + __expf(-x)); }

__device__ __forceinline__ uint32_t smem_u32(const void* p) {
    uint32_t a;
    asm("{ .reg .u64 t; cvta.to.shared.u64 t, %1; cvt.u32.u64 %0, t; }" : "=r"(a) : "l"(p));
    return a;
}
__device__ __forceinline__ void cp16(uint32_t dst, const void* src) {
    asm volatile("cp.async.cg.shared.global [%0], [%1], 16;" :: "r"(dst), "l"(src) : "memory");
}
__device__ __forceinline__ void ldsm_x4(uint32_t* r, uint32_t addr) {
    asm volatile("ldmatrix.sync.aligned.m8n8.x4.shared.b16 {%0,%1,%2,%3}, [%4];"
                 : "=r"(r[0]), "=r"(r[1]), "=r"(r[2]), "=r"(r[3]) : "r"(addr));
}
__device__ __forceinline__ void mma16816(float* d, const uint32_t* a, const uint32_t* b) {
    asm volatile(
        "mma.sync.aligned.m16n8k16.row.col.f32.f16.f16.f32 "
        "{%0,%1,%2,%3}, {%4,%5,%6,%7}, {%8,%9}, {%0,%1,%2,%3};"
        : "+f"(d[0]), "+f"(d[1]), "+f"(d[2]), "+f"(d[3])
        : "r"(a[0]), "r"(a[1]), "r"(a[2]), "r"(a[3]), "r"(b[0]), "r"(b[1]));
}

// ================= K0: prep_e + weight transpose + gather (branch by block) ==
__global__ void k_prep(const int* __restrict__ x, const float* __restrict__ embed,
                       const float* __restrict__ ggc,
                       const float* __restrict__ wih, const float* __restrict__ whh) {
    __shared__ float hs[Hh];
    int bid = blockIdx.x, t = threadIdx.x;
    if (bid < PE_BLKS) {
        // prep_e: embed -> fp16 rows (K=112, zero-padded)
        int idx = bid * 256 + t;          // pair index, always < Jpad*56
        int j  = idx / (KP/2);
        int kp = (idx - j * (KP/2)) * 2;
        __half o[2];
        #pragma unroll
        for (int i = 0; i < 2; i++) {
            int h = kp + i;
            float v = (j < Jn && h < Hh) ? embed[(size_t)j * Hh + h] : 0.0f;
            o[i] = __float2half(v);
        }
        *(uint32_t*)(g_epk + (size_t)j * KP + kp) = *(uint32_t*)o;
    } else if (bid < PE_BLKS + WT_BLKS) {
        // GRU weight transpose
        int i = (bid - PE_BLKS) * 256 + t;
        if (i < 300 * Hh) {
            int r = i / Hh, c = i % Hh;
            g_wihT[c * 300 + r] = wih[i];
            g_whhT[c * 300 + r] = whh[i];
        }
    } else {
        // gather + m = h @ ggc_w   (one block per node)
        int i = bid - (PE_BLKS + WT_BLKS);
        if (t < Hh) {
            float v = embed[(size_t)x[i] * Hh + t];
            hs[t] = v;
            g_h[i * Hh + t] = v;
            g_agg[i * Hh + t] = 0.0f;
        }
        __syncthreads();
        if (t < Hh) {
            float acc = 0.0f;
            #pragma unroll 4
            for (int c = 0; c < Hh; c++) acc = fmaf(hs[c], ggc[c * Hh + t], acc);
            g_m[i * Hh + t] = acc;
        }
    }
}

// ================= K1: scatter-add =================
__global__ void k_scatter(const int* __restrict__ ei, const float* __restrict__ ew) {
    int e = blockIdx.x, t = threadIdx.x;
    if (t < Hh) {
        int s = ei[e], d = ei[Ej + e];
        atomicAdd(&g_agg[d * Hh + t], ew[e] * g_m[s * Hh + t]);
    }
}

// ================= K2: GRU + attention + coef packing, per batch =============
// Block b: GRU for nodes b*16..b*16+15 (4 groups of 4, weight reuse), then
// attention readout, then writes g_cpk[b] (vt rows 0-15, v+sh rows 16-31) fp16.
__global__ void __launch_bounds__(416) k_ga(
    const float* __restrict__ bih, const float* __restrict__ bhh,
    const float* __restrict__ W1w, const float* __restrict__ W1b,
    const float* __restrict__ W2w, const float* __restrict__ W2b,
    const float* __restrict__ Wtw, const float* __restrict__ Wtb,
    const float* __restrict__ qw,  const float* __restrict__ qb,
    const float* __restrict__ W3w, const float* __restrict__ W3b) {
    __shared__ float a_s[Ll * Hh], h_s[Ll * Hh];
    __shared__ float gi_s[4][300], gh_s[4][300];
    __shared__ float v_s[Ll * Hh];              // GRU output = v
    __shared__ float t1[Hh], a_att[Ll * Hh], alpha_s[Ll], sg[Hh], sh_s[Hh];
    int b = blockIdx.x, t = threadIdx.x;
    int nb = b * Ll;

    for (int i = t; i < Ll * Hh; i += 416) {
        int n = i / Hh, c = i % Hh;
        a_s[i] = g_agg[(nb + n) * Hh + c];
        h_s[i] = g_h  [(nb + n) * Hh + c];
    }
    __syncthreads();

    // ---- GRU: 4 groups of 4 nodes ----
    for (int g = 0; g < 4; g++) {
        if (t < 300) {
            float ai0 = bih[t], ai1 = ai0, ai2 = ai0, ai3 = ai0;
            float ah0 = bhh[t], ah1 = ah0, ah2 = ah0, ah3 = ah0;
            const float* a0 = a_s + (4 * g) * Hh;
            const float* h0 = h_s + (4 * g) * Hh;
            #pragma unroll 4
            for (int c = 0; c < Hh; c++) {
                float wv = g_wihT[c * 300 + t];
                float uv = g_whhT[c * 300 + t];
                ai0 = fmaf(a0[c],          wv, ai0); ah0 = fmaf(h0[c],          uv, ah0);
                ai1 = fmaf(a0[Hh + c],     wv, ai1); ah1 = fmaf(h0[Hh + c],     uv, ah1);
                ai2 = fmaf(a0[2*Hh + c],   wv, ai2); ah2 = fmaf(h0[2*Hh + c],   uv, ah2);
                ai3 = fmaf(a0[3*Hh + c],   wv, ai3); ah3 = fmaf(h0[3*Hh + c],   uv, ah3);
            }
            gi_s[0][t] = ai0; gi_s[1][t] = ai1; gi_s[2][t] = ai2; gi_s[3][t] = ai3;
            gh_s[0][t] = ah0; gh_s[1][t] = ah1; gh_s[2][t] = ah2; gh_s[3][t] = ah3;
        }
        __syncthreads();
        if (t < 400) {
            int n = t / Hh, k = t % Hh;
            float r  = sigm(gi_s[n][k]         + gh_s[n][k]);
            float zg = sigm(gi_s[n][Hh + k]    + gh_s[n][Hh + k]);
            float ng = tanhf(gi_s[n][2*Hh + k] + r * gh_s[n][2*Hh + k]);
            v_s[(4 * g + n) * Hh + k] = (1.0f - zg) * ng + zg * h_s[(4 * g + n) * Hh + k];
        }
        __syncthreads();
    }

    // ---- attention readout ----
    if (t < Hh) {
        float acc = W1b[t];
        const float* w = W1w + t * Hh;
        #pragma unroll 4
        for (int c = 0; c < Hh; c++) acc = fmaf(v_s[15 * Hh + c], w[c], acc);
        t1[t] = acc;
    }
    __syncthreads();

    for (int idx = t; idx < Ll * Hh; idx += 416) {
        int l = idx / Hh, k = idx % Hh;
        float acc = W2b[k];
        const float* w = W2w + k * Hh;
        const float* vrow = v_s + l * Hh;
        #pragma unroll 4
        for (int c = 0; c < Hh; c++) acc = fmaf(vrow[c], w[c], acc);
        a_att[idx] = sigm(t1[k] + acc);
    }
    __syncthreads();

    if (t < Ll) {
        float acc = qb[0];
        #pragma unroll 4
        for (int k = 0; k < Hh; k++) acc = fmaf(a_att[t * Hh + k], qw[k], acc);
        alpha_s[t] = acc;
    }
    __syncthreads();

    if (t < Hh) {
        float acc = 0.0f;
        #pragma unroll
        for (int l = 0; l < Ll; l++) acc = fmaf(alpha_s[l], v_s[l * Hh + t], acc);
        sg[t] = acc;
    }
    __syncthreads();

    if (t < Hh) {
        float acc = W3b[t];
        const float* w = W3w + t * 2 * Hh;
        #pragma unroll 4
        for (int c = 0; c < Hh; c++)
            acc = fmaf(v_s[15 * Hh + c], w[c], fmaf(sg[c], w[Hh + c], acc));
        sh_s[t] = acc;
    }
    __syncthreads();

    // ---- pack coefs: rows 0-15 = vt, rows 16-31 = v + sh ----
    for (int idx = t; idx < Ll * Hh; idx += 416) {
        int l = idx / Hh, k = idx % Hh;
        float acc = Wtb[k];
        const float* w = Wtw + k * Hh;
        const float* vrow = v_s + l * Hh;
        #pragma unroll 4
        for (int c = 0; c < Hh; c++) acc = fmaf(vrow[c], w[c], acc);
        g_cpk[((size_t)b * 32 + l) * KP + k]      = __float2half(acc);
        g_cpk[((size_t)b * 32 + 16 + l) * KP + k] = __float2half(v_s[l * Hh + k] + sh_s[k]);
    }
}

// ================= K3: HMMA fused GEMM + softmax epilogue (unchanged) ========
__global__ void __launch_bounds__(256, 3) k_ztc(float* __restrict__ z) {
    extern __shared__ __align__(128) char sm[];
    const uint32_t smA = smem_u32(sm);
    const uint32_t smB = smA + SM_A;
    int tid = threadIdx.x, warp = tid >> 5, lane = tid & 31;
    int wr = warp >> 1, wc = warp & 1;
    int jt = blockIdx.x, bs = blockIdx.y;      // bs: 0..3, 16 batches each

    // load A tile (128 rows x 224B)
    {
        const char* src = (const char*)g_epk + (size_t)jt * JT * RB;
        for (int i = tid; i < JT * 14; i += 256) {
            int r = i / 14, c = i - r * 14;
            cp16(smA + (uint32_t)r * ST + c * 16, src + (size_t)r * RB + c * 16);
        }
    }
    // load B for bt=0 (2 batches x 32 rows x 224B)
    {
        const char* src = (const char*)g_cpk + (size_t)(bs * 16) * 32 * RB;
        for (int i = tid; i < 64 * 14; i += 256) {
            int r = i / 14, c = i - r * 14;
            cp16(smB + (uint32_t)r * ST + c * 16, src + (size_t)r * RB + c * 16);
        }
    }
    asm volatile("cp.async.commit_group;" ::: "memory");
    asm volatile("cp.async.wait_group 0;" ::: "memory");
    __syncthreads();

    const uint32_t aBase = smA + (uint32_t)(wr * 32 + (lane & 15)) * ST + ((lane >> 4) << 4);
    const uint32_t bOff4 = (uint32_t)(wc * 32 + (lane & 7) + ((lane >> 4) << 3)) * ST
                         + (((lane >> 3) & 1) << 4);

    #pragma unroll 1
    for (int bt = 0; bt < 8; bt++) {
        if (bt + 1 < 8) {
            const char* src = (const char*)g_cpk + (size_t)(bs * 16 + (bt + 1) * 2) * 32 * RB;
            uint32_t dst = smB + (uint32_t)((bt + 1) & 1) * SM_B;
            for (int i = tid; i < 64 * 14; i += 256) {
                int r = i / 14, c = i - r * 14;
                cp16(dst + (uint32_t)r * ST + c * 16, src + (size_t)r * RB + c * 16);
            }
            asm volatile("cp.async.commit_group;" ::: "memory");
        }
        const uint32_t bBase = smB + (uint32_t)(bt & 1) * SM_B + bOff4;

        float acc[2][4][4];
        #pragma unroll
        for (int mt = 0; mt < 2; mt++)
            #pragma unroll
            for (int nt = 0; nt < 4; nt++)
                #pragma unroll
                for (int q = 0; q < 4; q++) acc[mt][nt][q] = 0.0f;

        #pragma unroll
        for (int ksi = 0; ksi < 7; ksi++) {
            uint32_t af[2][4], bf[2][4];
            #pragma unroll
            for (int mt = 0; mt < 2; mt++)
                ldsm_x4(af[mt], aBase + (uint32_t)mt * (16 * ST) + ksi * 32);
            #pragma unroll
            for (int np = 0; np < 2; np++)
                ldsm_x4(bf[np], bBase + (uint32_t)np * (16 * ST) + ksi * 32);
            #pragma unroll
            for (int np = 0; np < 2; np++) {
                #pragma unroll
                for (int mt = 0; mt < 2; mt++) {
                    mma16816(acc[mt][2 * np],     af[mt], bf[np]);
                    mma16816(acc[mt][2 * np + 1], af[mt], bf[np] + 2);
                }
            }
        }

        int b = bs * 16 + bt * 2 + wc;
        #pragma unroll
        for (int mt = 0; mt < 2; mt++) {
            int jA = jt * JT + wr * 32 + mt * 16 + (lane >> 2);
            #pragma unroll
            for (int half = 0; half < 2; half++) {
                int q0 = half * 2, q1 = half * 2 + 1;
                float p0 = acc[mt][0][q0], p1 = acc[mt][0][q1];
                float p2 = acc[mt][1][q0], p3 = acc[mt][1][q1];
                float c0 = acc[mt][2][q0], c1 = acc[mt][2][q1];
                float c2 = acc[mt][3][q0], c3 = acc[mt][3][q1];
                float m = fmaxf(fmaxf(p0, p1), fmaxf(p2, p3));
                m = fmaxf(m, __shfl_xor_sync(0xffffffffu, m, 1));
                m = fmaxf(m, __shfl_xor_sync(0xffffffffu, m, 2));
                float e0 = __expf(p0 - m), e1 = __expf(p1 - m);
                float e2 = __expf(p2 - m), e3 = __expf(p3 - m);
                float se = e0 + e1 + e2 + e3;
                float ac = fmaf(e0, c0, fmaf(e1, c1, fmaf(e2, c2, e3 * c3)));
                se += __shfl_xor_sync(0xffffffffu, se, 1);
                ac += __shfl_xor_sync(0xffffffffu, ac, 1);
                se += __shfl_xor_sync(0xffffffffu, se, 2);
                ac += __shfl_xor_sync(0xffffffffu, ac, 2);
                int j = jA + half * 8;
                if ((lane & 3) == 0 && j < Jn)
                    z[(size_t)b * Jn + j] = ac / se;
            }
        }

        if (bt + 1 < 8) asm volatile("cp.async.wait_group 0;" ::: "memory");
        __syncthreads();
    }
}

// ================= launch =================
extern "C" void kernel_launch(void* const* d_in, const int* in_sizes, int n_in,
                              void* d_out, int out_size) {
    const int*   x     = (const int*)  d_in[0];
    const int*   ei    = (const int*)  d_in[1];
    const float* ew    = (const float*)d_in[2];
    const float* embed = (const float*)d_in[4];
    const float* ggc   = (const float*)d_in[5];
    const float* wih   = (const float*)d_in[6];
    const float* whh   = (const float*)d_in[7];
    const float* bih   = (const float*)d_in[8];
    const float* bhh   = (const float*)d_in[9];
    const float* W1w   = (const float*)d_in[10];
    const float* W1b   = (const float*)d_in[11];
    const float* W2w   = (const float*)d_in[12];
    const float* W2b   = (const float*)d_in[13];
    const float* Wtw   = (const float*)d_in[14];
    const float* Wtb   = (const float*)d_in[15];
    const float* qw    = (const float*)d_in[16];
    const float* qb    = (const float*)d_in[17];
    const float* W3w   = (const float*)d_in[18];
    const float* W3b   = (const float*)d_in[19];
    float* z = (float*)d_out;

    cudaFuncSetAttribute(k_ztc, cudaFuncAttributeMaxDynamicSharedMemorySize, SM_TOTAL);

    k_prep<<<K0_GRID, 256>>>(x, embed, ggc, wih, whh);          // launch 0
    k_scatter<<<Ej, 128>>>(ei, ew);                             // launch 1
    k_ga<<<Bb, 416>>>(bih, bhh, W1w, W1b, W2w, W2b,             // launch 2
                      Wtw, Wtb, qw, qb, W3w, W3b);
    k_ztc<<<dim3(NJT, 4), 256, SM_TOTAL>>>(z);                  // launch 3 -> profiled
}